// round 14
// baseline (speedup 1.0000x reference)
#include <cuda_runtime.h>
#include <cuda_bf16.h>
#include <cstdint>
#include <math.h>
#include <float.h>

// ---------------- problem constants ----------------
#define B_   8
#define E_   256
#define N_   32
#define D_   512
#define RD_  768
#define R_   2000
#define L_   2
#define K_   8
#define M_   32
#define HEADS_ 8
#define DH_  64
#define HLLM_ 4096
#define BE_  (B_*E_)      // 2048
#define BM_  (B_*M_)      // 256
#define KS_  4            // split-K factor for w2

#define GA_STRIDE 36
#define GA_SMEM   (3*64*GA_STRIDE*4*2)          // 55296 B  (gemmA 64x64, 3-stage)
#define GB_SMEM   (3*(128+64)*GA_STRIDE*4)      // 82944 B  (gemmB 128x64, 3-stage)
#define GS_SMEM   (2*4*64*GA_STRIDE*4)          // 73728 B  (gemmA_split)

// ---------------- scratch ----------------
__device__ float g_relproj[R_*D_];
__device__ float g_inorm[R_];
__device__ float g_states[BE_*D_];
__device__ float g_agg[BE_*D_];
__device__ float g_attn0[BE_*D_];
__device__ float g_attn1[BE_*D_];
__device__ float g_h[BE_*4*D_];
__device__ float g_part[KS_*BE_*D_];
__device__ float g_wc[2*D_*D_];
__device__ float g_bc[2*D_];
__device__ float g_zero[D_];
__device__ float g_q[M_*D_];
__device__ float g_k[BE_*D_];
__device__ float g_v[BE_*D_];
__device__ float g_mem[BM_*D_];
__device__ float g_memo[BM_*D_];
__device__ float g_noedge[B_];
__device__ float g_w1r[(size_t)L_*4*D_*D_];
__device__ float g_w2r[(size_t)L_*4*D_*D_];
__device__ float g_kvwr[2*D_*D_];
__device__ float g_pwr[(size_t)HLLM_*D_];
__device__ float g_owr[2*D_*D_];
__device__ float g_vwT[2*D_*D_];
__device__ float g_qr[M_*D_];
__device__ float g_qwr[D_*D_];
__device__ float g_towr[D_*D_];
__device__ float g_ehi[(size_t)R_*RD_];
__device__ float g_elo[(size_t)R_*RD_];
__device__ float g_whi[(size_t)D_*RD_];
__device__ float g_wlo[(size_t)D_*RD_];

// ---------------- tf32 helpers ----------------
__device__ __forceinline__ unsigned f2tf32(float f) {
    unsigned u;
    asm("cvt.rna.tf32.f32 %0, %1;" : "=r"(u) : "f"(f));
    return u;
}
__device__ __forceinline__ float rtf(float f) { return __uint_as_float(f2tf32(f)); }
__device__ __forceinline__ void mma_tf32(float c[4], const unsigned a[4], const unsigned b[2]) {
    asm volatile(
        "mma.sync.aligned.m16n8k8.row.col.f32.tf32.tf32.f32 "
        "{%0,%1,%2,%3}, {%4,%5,%6,%7}, {%8,%9}, {%0,%1,%2,%3};"
        : "+f"(c[0]), "+f"(c[1]), "+f"(c[2]), "+f"(c[3])
        : "r"(a[0]), "r"(a[1]), "r"(a[2]), "r"(a[3]), "r"(b[0]), "r"(b[1]));
}
__device__ __forceinline__ void cp16(unsigned int saddr, const float* gaddr, int sz) {
    asm volatile("cp.async.cg.shared.global [%0], [%1], 16, %2;"
                 :: "r"(saddr), "l"(gaddr), "r"(sz));
}

// ---------------- merged 9-segment tf32 pre-round ----------------
struct RoundSegs {
    const float* s[9];
    float* d[9];
    int n[9];
};
__global__ void round_allN(RoundSegs seg)
{
    int i = blockIdx.x * 256 + threadIdx.x;
    #pragma unroll
    for (int k = 0; k < 9; k++) {
        if (i < seg.n[k]) {
            float4 v = *(const float4*)&seg.s[k][(size_t)i * 4];
            v.x = rtf(v.x); v.y = rtf(v.y); v.z = rtf(v.z); v.w = rtf(v.w);
            *(float4*)&seg.d[k][(size_t)i * 4] = v;
            return;
        }
        i -= seg.n[k];
    }
}

// ---------------- hi/lo split prep ----------------
__global__ void round_split2(const float* __restrict__ s0, float* __restrict__ h0,
                             float* __restrict__ l0, int n0,
                             const float* __restrict__ s1, float* __restrict__ h1,
                             float* __restrict__ l1, int n1)
{
    int i = blockIdx.x * 256 + threadIdx.x;
    const float* s; float *h, *l;
    if (i < n0) { s = s0; h = h0; l = l0; }
    else if ((i -= n0) < n1) { s = s1; h = h1; l = l1; }
    else return;
    float4 v = *(const float4*)&s[(size_t)i * 4];
    float4 hv, lv;
    hv.x = rtf(v.x); lv.x = rtf(v.x - hv.x);
    hv.y = rtf(v.y); lv.y = rtf(v.y - hv.y);
    hv.z = rtf(v.z); lv.z = rtf(v.z - hv.z);
    hv.w = rtf(v.w); lv.w = rtf(v.w - hv.w);
    *(float4*)&h[(size_t)i * 4] = hv;
    *(float4*)&l[(size_t)i * 4] = lv;
}

// ---------------- transpose + round ----------------
__global__ void transpose_round(const float* __restrict__ src, float* __restrict__ dst)
{
    __shared__ float tile[32][33];
    int l  = blockIdx.z;
    int i0 = blockIdx.y * 32, j0 = blockIdx.x * 32;
    int tx = threadIdx.x & 31, ty = threadIdx.x >> 5;
    #pragma unroll
    for (int r = ty; r < 32; r += 8)
        tile[r][tx] = src[(size_t)l*D_*D_ + (size_t)(i0+r)*D_ + j0+tx];
    __syncthreads();
    #pragma unroll
    for (int r = ty; r < 32; r += 8)
        dst[(size_t)l*D_*D_ + (size_t)(j0+r)*D_ + i0+tx] = rtf(tile[tx][r]);
}

// ---------------- cp.async tf32 NT GEMM, 64x64, BK=32, 3-stage ----------------
template<bool SK>
__global__ __launch_bounds__(128) void gemmA(
    const float* __restrict__ A0, const float* __restrict__ A1,
    const float* __restrict__ W0, const float* __restrict__ bias0, float* __restrict__ C0,
    const float* __restrict__ W1, const float* __restrict__ bias1, float* __restrict__ C1,
    int Mr, int Nc, int Kd, int act, int nsplit)
{
    extern __shared__ float dsm[];
    float (*As)[GA_STRIDE] = (float(*)[GA_STRIDE])dsm;
    float (*Ws)[GA_STRIDE] = (float(*)[GA_STRIDE])(dsm + 3*64*GA_STRIDE);

    const float* A;
    const float* W;
    const float* bias;
    float* C;
    int kbase = 0, nIter;
    if (SK) {
        A = A0; W = W0; bias = bias0;
        const int Kc = Kd / nsplit;
        kbase = blockIdx.z * Kc;
        nIter = Kc / 32;
        C = C0 + (size_t)blockIdx.z * Mr * Nc;
    } else {
        A    = blockIdx.z ? A1 : A0;
        W    = blockIdx.z ? W1 : W0;
        bias = blockIdx.z ? bias1 : bias0;
        C    = blockIdx.z ? C1 : C0;
        nIter = Kd / 32;
    }

    const int tid  = threadIdx.x;
    const int warp = tid >> 5, lane = tid & 31;
    const int wy   = warp >> 1, wx = warp & 1;
    const int grp  = lane >> 2, tig = lane & 3;
    const int row0 = blockIdx.y * 64;
    const int col0 = blockIdx.x * 64;
    const int lr   = tid >> 3;
    const int lk   = (tid & 7) * 4;

    const unsigned int sA = (unsigned int)__cvta_generic_to_shared(dsm);
    const unsigned int sW = (unsigned int)__cvta_generic_to_shared(dsm + 3*64*GA_STRIDE);
    const int v0s = (row0 + lr      < Mr) ? 16 : 0;
    const int v1s = (row0 + lr + 16 < Mr) ? 16 : 0;
    const int v2s = (row0 + lr + 32 < Mr) ? 16 : 0;
    const int v3s = (row0 + lr + 48 < Mr) ? 16 : 0;

    float acc[2][4][4] = {};

    #define ISSUE(st, itv)                                                              \
    {                                                                                   \
        const int k0 = kbase + (itv) * 32;                                              \
        cp16(sA + (((st)*64 + lr     )*GA_STRIDE + lk)*4, &A[(size_t)(row0+lr   ) * Kd + k0 + lk], v0s); \
        cp16(sA + (((st)*64 + lr + 16)*GA_STRIDE + lk)*4, &A[(size_t)(row0+lr+16) * Kd + k0 + lk], v1s); \
        cp16(sA + (((st)*64 + lr + 32)*GA_STRIDE + lk)*4, &A[(size_t)(row0+lr+32) * Kd + k0 + lk], v2s); \
        cp16(sA + (((st)*64 + lr + 48)*GA_STRIDE + lk)*4, &A[(size_t)(row0+lr+48) * Kd + k0 + lk], v3s); \
        cp16(sW + (((st)*64 + lr     )*GA_STRIDE + lk)*4, &W[(size_t)(col0+lr   ) * Kd + k0 + lk], 16); \
        cp16(sW + (((st)*64 + lr + 16)*GA_STRIDE + lk)*4, &W[(size_t)(col0+lr+16) * Kd + k0 + lk], 16); \
        cp16(sW + (((st)*64 + lr + 32)*GA_STRIDE + lk)*4, &W[(size_t)(col0+lr+32) * Kd + k0 + lk], 16); \
        cp16(sW + (((st)*64 + lr + 48)*GA_STRIDE + lk)*4, &W[(size_t)(col0+lr+48) * Kd + k0 + lk], 16); \
    }

    ISSUE(0, 0);
    asm volatile("cp.async.commit_group;");
    if (nIter > 1) ISSUE(1, 1);
    asm volatile("cp.async.commit_group;");

    for (int it = 0; it < nIter; it++) {
        asm volatile("cp.async.wait_group 1;");
        __syncthreads();

        if (it + 2 < nIter) ISSUE((it + 2) % 3, it + 2);
        asm volatile("cp.async.commit_group;");

        const int buf = it % 3;
        #pragma unroll
        for (int ks = 0; ks < 4; ks++) {
            const int kb = ks * 8;
            unsigned aH[2][4], bH[4][2];
            #pragma unroll
            for (int mt = 0; mt < 2; mt++) {
                const int mr = buf * 64 + wy * 32 + mt * 16 + grp;
                aH[mt][0] = __float_as_uint(As[mr    ][kb + tig]);
                aH[mt][1] = __float_as_uint(As[mr + 8][kb + tig]);
                aH[mt][2] = __float_as_uint(As[mr    ][kb + tig + 4]);
                aH[mt][3] = __float_as_uint(As[mr + 8][kb + tig + 4]);
            }
            #pragma unroll
            for (int nt = 0; nt < 4; nt++) {
                const int nc = buf * 64 + wx * 32 + nt * 8 + grp;
                bH[nt][0] = __float_as_uint(Ws[nc][kb + tig]);
                bH[nt][1] = __float_as_uint(Ws[nc][kb + tig + 4]);
            }
            #pragma unroll
            for (int mt = 0; mt < 2; mt++)
                #pragma unroll
                for (int nt = 0; nt < 4; nt++)
                    mma_tf32(acc[mt][nt], aH[mt], bH[nt]);
        }
        __syncthreads();
    }
    #undef ISSUE

    #pragma unroll
    for (int mt = 0; mt < 2; mt++) {
        const int r0 = row0 + wy * 32 + mt * 16 + grp;
        const int r1 = r0 + 8;
        #pragma unroll
        for (int nt = 0; nt < 4; nt++) {
            const int gc = col0 + wx * 32 + nt * 8 + tig * 2;
            float v0 = acc[mt][nt][0], v1 = acc[mt][nt][1];
            float v2 = acc[mt][nt][2], v3 = acc[mt][nt][3];
            if (!SK) {
                const float b0 = bias[gc], b1 = bias[gc + 1];
                v0 += b0; v1 += b1; v2 += b0; v3 += b1;
                if (act == 1) {
                    v0 = rtf(0.5f * v0 * (1.f + erff(v0 * 0.70710678118654752f)));
                    v1 = rtf(0.5f * v1 * (1.f + erff(v1 * 0.70710678118654752f)));
                    v2 = rtf(0.5f * v2 * (1.f + erff(v2 * 0.70710678118654752f)));
                    v3 = rtf(0.5f * v3 * (1.f + erff(v3 * 0.70710678118654752f)));
                } else if (act == 2) {
                    v0 = rtf(v0); v1 = rtf(v1); v2 = rtf(v2); v3 = rtf(v3);
                }
            }
            if (r0 < Mr) *(float2*)&C[(size_t)r0 * Nc + gc] = make_float2(v0, v1);
            if (r1 < Mr) *(float2*)&C[(size_t)r1 * Nc + gc] = make_float2(v2, v3);
        }
    }
}

// ---------------- cp.async tf32 NT GEMM, 128x64 tile, 256 threads, 3-stage --------
// For M % 128 == 0 shapes (no row guards). SK: split-K partials.
template<bool SK>
__global__ __launch_bounds__(256) void gemmB(
    const float* __restrict__ A0, const float* __restrict__ A1,
    const float* __restrict__ W0, const float* __restrict__ bias0, float* __restrict__ C0,
    const float* __restrict__ W1, const float* __restrict__ bias1, float* __restrict__ C1,
    int Mr, int Nc, int Kd, int act, int nsplit)
{
    extern __shared__ float dsm[];
    float (*As)[GA_STRIDE] = (float(*)[GA_STRIDE])dsm;                        // [3*128][36]
    float (*Ws)[GA_STRIDE] = (float(*)[GA_STRIDE])(dsm + 3*128*GA_STRIDE);    // [3*64][36]

    const float* A;
    const float* W;
    const float* bias;
    float* C;
    int kbase = 0, nIter;
    if (SK) {
        A = A0; W = W0; bias = bias0;
        const int Kc = Kd / nsplit;
        kbase = blockIdx.z * Kc;
        nIter = Kc / 32;
        C = C0 + (size_t)blockIdx.z * Mr * Nc;
    } else {
        A    = blockIdx.z ? A1 : A0;
        W    = blockIdx.z ? W1 : W0;
        bias = blockIdx.z ? bias1 : bias0;
        C    = blockIdx.z ? C1 : C0;
        nIter = Kd / 32;
    }

    const int tid  = threadIdx.x;
    const int warp = tid >> 5, lane = tid & 31;
    const int wy   = warp >> 1, wx = warp & 1;    // 4x2 warps: rows wy*32, cols wx*32
    const int grp  = lane >> 2, tig = lane & 3;
    const int row0 = blockIdx.y * 128;
    const int col0 = blockIdx.x * 64;
    const int lr   = tid >> 3;                    // 0..31
    const int lk   = (tid & 7) * 4;

    const unsigned int sA = (unsigned int)__cvta_generic_to_shared(dsm);
    const unsigned int sW = (unsigned int)__cvta_generic_to_shared(dsm + 3*128*GA_STRIDE);

    float acc[2][4][4] = {};

    #define BISSUE(st, itv)                                                             \
    {                                                                                   \
        const int k0 = kbase + (itv) * 32;                                              \
        cp16(sA + (((st)*128 + lr     )*GA_STRIDE + lk)*4, &A[(size_t)(row0+lr   ) * Kd + k0 + lk], 16); \
        cp16(sA + (((st)*128 + lr + 32)*GA_STRIDE + lk)*4, &A[(size_t)(row0+lr+32) * Kd + k0 + lk], 16); \
        cp16(sA + (((st)*128 + lr + 64)*GA_STRIDE + lk)*4, &A[(size_t)(row0+lr+64) * Kd + k0 + lk], 16); \
        cp16(sA + (((st)*128 + lr + 96)*GA_STRIDE + lk)*4, &A[(size_t)(row0+lr+96) * Kd + k0 + lk], 16); \
        cp16(sW + (((st)*64  + lr     )*GA_STRIDE + lk)*4, &W[(size_t)(col0+lr   ) * Kd + k0 + lk], 16); \
        cp16(sW + (((st)*64  + lr + 32)*GA_STRIDE + lk)*4, &W[(size_t)(col0+lr+32) * Kd + k0 + lk], 16); \
    }

    BISSUE(0, 0);
    asm volatile("cp.async.commit_group;");
    if (nIter > 1) BISSUE(1, 1);
    asm volatile("cp.async.commit_group;");

    for (int it = 0; it < nIter; it++) {
        asm volatile("cp.async.wait_group 1;");
        __syncthreads();

        if (it + 2 < nIter) BISSUE((it + 2) % 3, it + 2);
        asm volatile("cp.async.commit_group;");

        const int buf = it % 3;
        #pragma unroll
        for (int ks = 0; ks < 4; ks++) {
            const int kb = ks * 8;
            unsigned aH[2][4], bH[4][2];
            #pragma unroll
            for (int mt = 0; mt < 2; mt++) {
                const int mr = buf * 128 + wy * 32 + mt * 16 + grp;
                aH[mt][0] = __float_as_uint(As[mr    ][kb + tig]);
                aH[mt][1] = __float_as_uint(As[mr + 8][kb + tig]);
                aH[mt][2] = __float_as_uint(As[mr    ][kb + tig + 4]);
                aH[mt][3] = __float_as_uint(As[mr + 8][kb + tig + 4]);
            }
            #pragma unroll
            for (int nt = 0; nt < 4; nt++) {
                const int nc = buf * 64 + wx * 32 + nt * 8 + grp;
                bH[nt][0] = __float_as_uint(Ws[nc][kb + tig]);
                bH[nt][1] = __float_as_uint(Ws[nc][kb + tig + 4]);
            }
            #pragma unroll
            for (int mt = 0; mt < 2; mt++)
                #pragma unroll
                for (int nt = 0; nt < 4; nt++)
                    mma_tf32(acc[mt][nt], aH[mt], bH[nt]);
        }
        __syncthreads();
    }
    #undef BISSUE

    #pragma unroll
    for (int mt = 0; mt < 2; mt++) {
        const int r0 = row0 + wy * 32 + mt * 16 + grp;
        const int r1 = r0 + 8;
        #pragma unroll
        for (int nt = 0; nt < 4; nt++) {
            const int gc = col0 + wx * 32 + nt * 8 + tig * 2;
            float v0 = acc[mt][nt][0], v1 = acc[mt][nt][1];
            float v2 = acc[mt][nt][2], v3 = acc[mt][nt][3];
            if (!SK) {
                const float b0 = bias[gc], b1 = bias[gc + 1];
                v0 += b0; v1 += b1; v2 += b0; v3 += b1;
                if (act == 1) {
                    v0 = rtf(0.5f * v0 * (1.f + erff(v0 * 0.70710678118654752f)));
                    v1 = rtf(0.5f * v1 * (1.f + erff(v1 * 0.70710678118654752f)));
                    v2 = rtf(0.5f * v2 * (1.f + erff(v2 * 0.70710678118654752f)));
                    v3 = rtf(0.5f * v3 * (1.f + erff(v3 * 0.70710678118654752f)));
                } else if (act == 2) {
                    v0 = rtf(v0); v1 = rtf(v1); v2 = rtf(v2); v3 = rtf(v3);
                }
            }
            *(float2*)&C[(size_t)r0 * Nc + gc] = make_float2(v0, v1);
            *(float2*)&C[(size_t)r1 * Nc + gc] = make_float2(v2, v3);
        }
    }
}

// ---------------- cp.async split-tf32 GEMM (relproj) ----------------
__global__ __launch_bounds__(128) void gemmA_split(
    const float* __restrict__ Ahi, const float* __restrict__ Alo,
    const float* __restrict__ Whi, const float* __restrict__ Wlo,
    const float* __restrict__ bias, float* __restrict__ C,
    int Mr, int Nc, int Kd)
{
    extern __shared__ float dsm[];
    float (*SM)[GA_STRIDE] = (float(*)[GA_STRIDE])dsm;

    const int tid  = threadIdx.x;
    const int warp = tid >> 5, lane = tid & 31;
    const int wy   = warp >> 1, wx = warp & 1;
    const int grp  = lane >> 2, tig = lane & 3;
    const int row0 = blockIdx.y * 64;
    const int col0 = blockIdx.x * 64;
    const int lr   = tid >> 3;
    const int lk   = (tid & 7) * 4;

    const unsigned int sB = (unsigned int)__cvta_generic_to_shared(dsm);
    const int v0s = (row0 + lr      < Mr) ? 16 : 0;
    const int v1s = (row0 + lr + 16 < Mr) ? 16 : 0;
    const int v2s = (row0 + lr + 32 < Mr) ? 16 : 0;
    const int v3s = (row0 + lr + 48 < Mr) ? 16 : 0;

    const int nIter = Kd / 32;
    float acc[2][4][4] = {};

    #define SISSUE(st, itv)                                                             \
    {                                                                                   \
        const int k0 = (itv) * 32;                                                      \
        const int sb = (st) * 256;                                                      \
        cp16(sB + ((sb       + lr     )*GA_STRIDE + lk)*4, &Ahi[(size_t)(row0+lr   ) * Kd + k0 + lk], v0s); \
        cp16(sB + ((sb       + lr + 16)*GA_STRIDE + lk)*4, &Ahi[(size_t)(row0+lr+16) * Kd + k0 + lk], v1s); \
        cp16(sB + ((sb       + lr + 32)*GA_STRIDE + lk)*4, &Ahi[(size_t)(row0+lr+32) * Kd + k0 + lk], v2s); \
        cp16(sB + ((sb       + lr + 48)*GA_STRIDE + lk)*4, &Ahi[(size_t)(row0+lr+48) * Kd + k0 + lk], v3s); \
        cp16(sB + ((sb + 64  + lr     )*GA_STRIDE + lk)*4, &Alo[(size_t)(row0+lr   ) * Kd + k0 + lk], v0s); \
        cp16(sB + ((sb + 64  + lr + 16)*GA_STRIDE + lk)*4, &Alo[(size_t)(row0+lr+16) * Kd + k0 + lk], v1s); \
        cp16(sB + ((sb + 64  + lr + 32)*GA_STRIDE + lk)*4, &Alo[(size_t)(row0+lr+32) * Kd + k0 + lk], v2s); \
        cp16(sB + ((sb + 64  + lr + 48)*GA_STRIDE + lk)*4, &Alo[(size_t)(row0+lr+48) * Kd + k0 + lk], v3s); \
        cp16(sB + ((sb + 128 + lr     )*GA_STRIDE + lk)*4, &Whi[(size_t)(col0+lr   ) * Kd + k0 + lk], 16); \
        cp16(sB + ((sb + 128 + lr + 16)*GA_STRIDE + lk)*4, &Whi[(size_t)(col0+lr+16) * Kd + k0 + lk], 16); \
        cp16(sB + ((sb + 128 + lr + 32)*GA_STRIDE + lk)*4, &Whi[(size_t)(col0+lr+32) * Kd + k0 + lk], 16); \
        cp16(sB + ((sb + 128 + lr + 48)*GA_STRIDE + lk)*4, &Whi[(size_t)(col0+lr+48) * Kd + k0 + lk], 16); \
        cp16(sB + ((sb + 192 + lr     )*GA_STRIDE + lk)*4, &Wlo[(size_t)(col0+lr   ) * Kd + k0 + lk], 16); \
        cp16(sB + ((sb + 192 + lr + 16)*GA_STRIDE + lk)*4, &Wlo[(size_t)(col0+lr+16) * Kd + k0 + lk], 16); \
        cp16(sB + ((sb + 192 + lr + 32)*GA_STRIDE + lk)*4, &Wlo[(size_t)(col0+lr+32) * Kd + k0 + lk], 16); \
        cp16(sB + ((sb + 192 + lr + 48)*GA_STRIDE + lk)*4, &Wlo[(size_t)(col0+lr+48) * Kd + k0 + lk], 16); \
    }

    SISSUE(0, 0);
    asm volatile("cp.async.commit_group;");

    for (int it = 0; it < nIter; it++) {
        if (it + 1 < nIter) SISSUE((it + 1) & 1, it + 1);
        asm volatile("cp.async.commit_group;");
        asm volatile("cp.async.wait_group 1;");
        __syncthreads();

        const int sb = (it & 1) * 256;
        #pragma unroll
        for (int ks = 0; ks < 4; ks++) {
            const int kb = ks * 8;
            unsigned aH[2][4], aL[2][4], bH[4][2], bL[4][2];
            #pragma unroll
            for (int mt = 0; mt < 2; mt++) {
                const int mr = sb + wy * 32 + mt * 16 + grp;
                aH[mt][0] = __float_as_uint(SM[mr    ][kb + tig]);
                aH[mt][1] = __float_as_uint(SM[mr + 8][kb + tig]);
                aH[mt][2] = __float_as_uint(SM[mr    ][kb + tig + 4]);
                aH[mt][3] = __float_as_uint(SM[mr + 8][kb + tig + 4]);
                aL[mt][0] = __float_as_uint(SM[mr + 64    ][kb + tig]);
                aL[mt][1] = __float_as_uint(SM[mr + 64 + 8][kb + tig]);
                aL[mt][2] = __float_as_uint(SM[mr + 64    ][kb + tig + 4]);
                aL[mt][3] = __float_as_uint(SM[mr + 64 + 8][kb + tig + 4]);
            }
            #pragma unroll
            for (int nt = 0; nt < 4; nt++) {
                const int nc = sb + 128 + wx * 32 + nt * 8 + grp;
                bH[nt][0] = __float_as_uint(SM[nc][kb + tig]);
                bH[nt][1] = __float_as_uint(SM[nc][kb + tig + 4]);
                bL[nt][0] = __float_as_uint(SM[nc + 64][kb + tig]);
                bL[nt][1] = __float_as_uint(SM[nc + 64][kb + tig + 4]);
            }
            #pragma unroll
            for (int mt = 0; mt < 2; mt++)
                #pragma unroll
                for (int nt = 0; nt < 4; nt++) {
                    mma_tf32(acc[mt][nt], aH[mt], bH[nt]);
                    mma_tf32(acc[mt][nt], aH[mt], bL[nt]);
                    mma_tf32(acc[mt][nt], aL[mt], bH[nt]);
                }
        }
        __syncthreads();
    }
    #undef SISSUE

    #pragma unroll
    for (int mt = 0; mt < 2; mt++) {
        const int r0 = row0 + wy * 32 + mt * 16 + grp;
        const int r1 = r0 + 8;
        #pragma unroll
        for (int nt = 0; nt < 4; nt++) {
            const int gc = col0 + wx * 32 + nt * 8 + tig * 2;
            const float b0 = bias[gc], b1 = bias[gc + 1];
            if (r0 < Mr) *(float2*)&C[(size_t)r0 * Nc + gc] =
                make_float2(acc[mt][nt][0] + b0, acc[mt][nt][1] + b1);
            if (r1 < Mr) *(float2*)&C[(size_t)r1 * Nc + gc] =
                make_float2(acc[mt][nt][2] + b0, acc[mt][nt][3] + b1);
        }
    }
}

// ---------------- composed bias ----------------
__global__ void bias_combine(const float* __restrict__ ly_ow,
                             const float* __restrict__ ly_vb,
                             const float* __restrict__ ly_ob)
{
    int gw = blockIdx.x * 8 + (threadIdx.x >> 5);
    int lane = threadIdx.x & 31;
    int l = gw >> 9, row = gw & 511;
    const float* Ow = ly_ow + (size_t)l * D_ * D_ + (size_t)row * D_;
    const float* vb = ly_vb + (size_t)l * D_;
    float s = 0.f;
    #pragma unroll
    for (int k = 0; k < 4; k++) {
        int idx = (k * 32 + lane) * 4;
        float4 a = *(const float4*)&Ow[idx];
        float4 v = *(const float4*)&vb[idx];
        s += a.x * v.x + a.y * v.y + a.z * v.z + a.w * v.w;
    }
    #pragma unroll
    for (int o = 16; o; o >>= 1) s += __shfl_down_sync(0xffffffffu, s, o);
    if (lane == 0) g_bc[l * D_ + row] = s + ly_ob[l * D_ + row];
}

// ---------------- per-row inverse norm (warp per row) ----------------
__global__ void rownorm_kernel()
{
    int r = blockIdx.x * 8 + (threadIdx.x >> 5);
    int lane = threadIdx.x & 31;
    const float* row = &g_relproj[(size_t)r * D_];
    float s = 0.f;
    #pragma unroll
    for (int k = 0; k < 4; k++) {
        float4 v = *(const float4*)&row[(k * 32 + lane) * 4];
        s += v.x*v.x + v.y*v.y + v.z*v.z + v.w*v.w;
    }
    #pragma unroll
    for (int o = 16; o; o >>= 1) s += __shfl_down_sync(0xffffffffu, s, o);
    if (lane == 0) g_inorm[r] = 1.f / fmaxf(sqrtf(s), 1e-12f);
}

// ---------------- fused sims / top-8 / mean agg ----------------
__global__ void sims_topk_agg(const int* __restrict__ eids, const int* __restrict__ nids)
{
    int be = blockIdx.x;
    __shared__ float rn[D_];
    __shared__ float sims[N_];
    __shared__ int   topid[K_];

    int eid = eids[be];
    float ei = g_inorm[eid];
    for (int d = threadIdx.x; d < D_; d += 256) {
        float v = g_relproj[(size_t)eid * D_ + d];
        g_states[(size_t)be * D_ + d] = rtf(v);
        rn[d] = v * ei;
    }
    __syncthreads();

    int warp = threadIdx.x >> 5, lane = threadIdx.x & 31;
    for (int n = warp; n < N_; n += 8) {
        int nid = nids[(size_t)be * N_ + n];
        const float* row = &g_relproj[(size_t)nid * D_];
        float s = 0.f;
        for (int d = lane; d < D_; d += 32) s += row[d] * rn[d];
        #pragma unroll
        for (int o = 16; o; o >>= 1) s += __shfl_down_sync(0xffffffffu, s, o);
        if (lane == 0) sims[n] = s * g_inorm[nid];
    }
    __syncthreads();

    if (threadIdx.x == 0) {
        unsigned used = 0;
        for (int j = 0; j < K_; j++) {
            float best = -FLT_MAX; int bi = 0;
            for (int n = 0; n < N_; n++) {
                if ((used >> n) & 1u) continue;
                if (sims[n] > best) { best = sims[n]; bi = n; }
            }
            used |= 1u << bi;
            topid[j] = nids[(size_t)be * N_ + bi];
        }
    }
    __syncthreads();

    for (int d = threadIdx.x; d < D_; d += 256) {
        float acc = 0.f;
        #pragma unroll
        for (int j = 0; j < K_; j++) acc += g_relproj[(size_t)topid[j] * D_ + d];
        g_agg[(size_t)be * D_ + d] = rtf(acc * (1.f / K_));
    }
}

// ---------------- residual + layernorm; output tf32-rounded ----------
template<bool SKMODE>
__global__ void add_ln_kernel(const float* __restrict__ addp,
                              const float* __restrict__ bias,
                              const float* __restrict__ gamma, const float* __restrict__ beta,
                              const float* __restrict__ mask)
{
    int r = blockIdx.x;
    int t = threadIdx.x;
    __shared__ float red[256];

    float a0, a1;
    if (SKMODE) {
        size_t o0 = (size_t)r*D_ + t, o1 = o0 + 256;
        a0 = g_part[o0] + g_part[(size_t)BE_*D_ + o0] + g_part[2*(size_t)BE_*D_ + o0]
           + g_part[3*(size_t)BE_*D_ + o0] + bias[t];
        a1 = g_part[o1] + g_part[(size_t)BE_*D_ + o1] + g_part[2*(size_t)BE_*D_ + o1]
           + g_part[3*(size_t)BE_*D_ + o1] + bias[t + 256];
    } else {
        a0 = addp[(size_t)r*D_ + t];
        a1 = addp[(size_t)r*D_ + t + 256];
    }
    float x0 = g_states[(size_t)r*D_ + t]       + a0;
    float x1 = g_states[(size_t)r*D_ + t + 256] + a1;

    red[t] = x0 + x1;
    __syncthreads();
    for (int s = 128; s; s >>= 1) { if (t < s) red[t] += red[t+s]; __syncthreads(); }
    float mu = red[0] * (1.f / D_);
    __syncthreads();

    float d0 = x0 - mu, d1 = x1 - mu;
    red[t] = d0*d0 + d1*d1;
    __syncthreads();
    for (int s = 128; s; s >>= 1) { if (t < s) red[t] += red[t+s]; __syncthreads(); }
    float inv = rsqrtf(red[0] * (1.f / D_) + 1e-5f);

    float mf = mask ? mask[r] : 1.f;
    g_states[(size_t)r*D_ + t]       = rtf((d0 * inv * gamma[t]     + beta[t])     * mf);
    g_states[(size_t)r*D_ + t + 256] = rtf((d1 * inv * gamma[t+256] + beta[t+256]) * mf);
}

// ---------------- memory-token cross attention ----------------
#define ETILE 16
__global__ __launch_bounds__(256) void mem_attn2(const float* __restrict__ edge_mask)
{
    const int b = blockIdx.x >> 3;
    const int h = blockIdx.x & 7;
    const int tid = threadIdx.x;

    __shared__ float Qs[M_][DH_ + 1];
    __shared__ float S[M_][E_];
    __shared__ float KV[ETILE][DH_ + 1];

    for (int i = tid; i < M_ * DH_; i += 256) {
        int m = i >> 6, d = i & 63;
        Qs[m][d] = g_q[(size_t)m * D_ + h * DH_ + d];
    }

    const float* mk = &edge_mask[(size_t)b * E_];
    const float* kb = &g_k[(size_t)b * E_ * D_ + h * DH_];
    const float* vb = &g_v[(size_t)b * E_ * D_ + h * DH_];
    __syncthreads();

    for (int et = 0; et < E_ / ETILE; et++) {
        for (int i = tid; i < ETILE * DH_; i += 256) {
            int e = i >> 6, d = i & 63;
            KV[e][d] = kb[(size_t)(et * ETILE + e) * D_ + d];
        }
        __syncthreads();
        #pragma unroll
        for (int p = 0; p < 2; p++) {
            int idx = tid * 2 + p;
            int m = idx >> 4, e = idx & 15;
            float s = 0.f;
            #pragma unroll 8
            for (int d = 0; d < DH_; d++) s += Qs[m][d] * KV[e][d];
            int eg = et * ETILE + e;
            S[m][eg] = (mk[eg] == 0.f) ? -FLT_MAX : s * 0.125f;
        }
        __syncthreads();
    }

    {
        const int warp = tid >> 5, lane = tid & 31;
        for (int r = 0; r < 4; r++) {
            const int m = warp * 4 + r;
            float mx = -FLT_MAX;
            for (int e = lane; e < E_; e += 32) mx = fmaxf(mx, S[m][e]);
            #pragma unroll
            for (int o = 16; o; o >>= 1) mx = fmaxf(mx, __shfl_xor_sync(0xffffffffu, mx, o));
            float sum = 0.f;
            for (int e = lane; e < E_; e += 32) {
                float w = expf(S[m][e] - mx);
                S[m][e] = w;
                sum += w;
            }
            #pragma unroll
            for (int o = 16; o; o >>= 1) sum += __shfl_xor_sync(0xffffffffu, sum, o);
            float inv = 1.f / sum;
            for (int e = lane; e < E_; e += 32) S[m][e] *= inv;
        }
    }
    __syncthreads();

    const int m  = tid >> 3;
    const int d0 = (tid & 7) * 8;
    float acc[8] = {};
    for (int vt = 0; vt < E_ / ETILE; vt++) {
        for (int i = tid; i < ETILE * DH_; i += 256) {
            int e = i >> 6, d = i & 63;
            KV[e][d] = vb[(size_t)(vt * ETILE + e) * D_ + d];
        }
        __syncthreads();
        #pragma unroll
        for (int e = 0; e < ETILE; e++) {
            float w = S[m][vt * ETILE + e];
            #pragma unroll
            for (int j = 0; j < 8; j++) acc[j] += w * KV[e][d0 + j];
        }
        __syncthreads();
    }
    size_t o = (size_t)(b * M_ + m) * D_ + h * DH_ + d0;
    #pragma unroll
    for (int j = 0; j < 8; j++) g_mem[o + j] = rtf(acc[j]);
}

// ---------------- no-edge handling ----------------
__global__ void noedge_flags(const float* __restrict__ edge_mask)
{
    int b = blockIdx.x;
    __shared__ float red[256];
    red[threadIdx.x] = edge_mask[(size_t)b * E_ + threadIdx.x];
    __syncthreads();
    for (int s = 128; s; s >>= 1) { if (threadIdx.x < s) red[threadIdx.x] += red[threadIdx.x+s]; __syncthreads(); }
    if (threadIdx.x == 0) g_noedge[b] = (red[0] == 0.f) ? 0.f : 1.f;
}

__global__ void apply_noedge()
{
    int i = blockIdx.x * 256 + threadIdx.x;
    int b = i / (M_ * D_);
    g_memo[i] *= g_noedge[b];
}

// ---------------- host launch ----------------
static inline dim3 g64(int Mr, int Nc, int z = 1) {
    return dim3(Nc / 64, (Mr + 63) / 64, z);
}
static inline dim3 g128(int Mr, int Nc, int z = 1) {
    return dim3(Nc / 64, Mr / 128, z);
}

extern "C" void kernel_launch(void* const* d_in, const int* in_sizes, int n_in,
                              void* d_out, int out_size)
{
    const int*   edge_rel_ids = (const int*)  d_in[0];
    const int*   neigh_ids    = (const int*)  d_in[1];
    const float* edge_mask    = (const float*)d_in[2];
    const float* rel_emb      = (const float*)d_in[3];
    const float* rp_w         = (const float*)d_in[4];
    const float* rp_b         = (const float*)d_in[5];
    const float* ly_vw        = (const float*)d_in[6];
    const float* ly_vb        = (const float*)d_in[7];
    const float* ly_ow        = (const float*)d_in[8];
    const float* ly_ob        = (const float*)d_in[9];
    const float* ly_n1g       = (const float*)d_in[10];
    const float* ly_n1b       = (const float*)d_in[11];
    const float* ly_n2g       = (const float*)d_in[12];
    const float* ly_n2b       = (const float*)d_in[13];
    const float* ly_w1        = (const float*)d_in[14];
    const float* ly_b1        = (const float*)d_in[15];
    const float* ly_w2        = (const float*)d_in[16];
    const float* ly_b2        = (const float*)d_in[17];
    const float* mem_q        = (const float*)d_in[18];
    const float* t_qw         = (const float*)d_in[19];
    const float* t_qb         = (const float*)d_in[20];
    const float* t_kw         = (const float*)d_in[21];
    const float* t_kb         = (const float*)d_in[22];
    const float* t_vw         = (const float*)d_in[23];
    const float* t_vb         = (const float*)d_in[24];
    const float* t_ow         = (const float*)d_in[25];
    const float* t_ob         = (const float*)d_in[26];
    const float* proj_w       = (const float*)d_in[27];
    const float* proj_b       = (const float*)d_in[28];
    float* out = (float*)d_out;

    float *p_relproj, *p_states, *p_agg, *p_attn0, *p_attn1, *p_h, *p_part;
    float *p_wc, *p_bc, *p_zero, *p_q, *p_k, *p_v, *p_mem, *p_memo;
    float *p_w1r, *p_w2r, *p_kvwr, *p_pwr, *p_owr, *p_vwT, *p_qr, *p_qwr, *p_towr;
    float *p_ehi, *p_elo, *p_whi, *p_wlo;
    cudaGetSymbolAddress((void**)&p_relproj, g_relproj);
    cudaGetSymbolAddress((void**)&p_states,  g_states);
    cudaGetSymbolAddress((void**)&p_agg,     g_agg);
    cudaGetSymbolAddress((void**)&p_attn0,   g_attn0);
    cudaGetSymbolAddress((void**)&p_attn1,   g_attn1);
    cudaGetSymbolAddress((void**)&p_h,       g_h);
    cudaGetSymbolAddress((void**)&p_part,    g_part);
    cudaGetSymbolAddress((void**)&p_wc,      g_wc);
    cudaGetSymbolAddress((void**)&p_bc,      g_bc);
    cudaGetSymbolAddress((void**)&p_zero,    g_zero);
    cudaGetSymbolAddress((void**)&p_q,       g_q);
    cudaGetSymbolAddress((void**)&p_k,       g_k);
    cudaGetSymbolAddress((void**)&p_v,       g_v);
    cudaGetSymbolAddress((void**)&p_mem,     g_mem);
    cudaGetSymbolAddress((void**)&p_memo,    g_memo);
    cudaGetSymbolAddress((void**)&p_w1r,     g_w1r);
    cudaGetSymbolAddress((void**)&p_w2r,     g_w2r);
    cudaGetSymbolAddress((void**)&p_kvwr,    g_kvwr);
    cudaGetSymbolAddress((void**)&p_pwr,     g_pwr);
    cudaGetSymbolAddress((void**)&p_owr,     g_owr);
    cudaGetSymbolAddress((void**)&p_vwT,     g_vwT);
    cudaGetSymbolAddress((void**)&p_qr,      g_qr);
    cudaGetSymbolAddress((void**)&p_qwr,     g_qwr);
    cudaGetSymbolAddress((void**)&p_towr,    g_towr);
    cudaGetSymbolAddress((void**)&p_ehi,     g_ehi);
    cudaGetSymbolAddress((void**)&p_elo,     g_elo);
    cudaGetSymbolAddress((void**)&p_whi,     g_whi);
    cudaGetSymbolAddress((void**)&p_wlo,     g_wlo);

    cudaFuncSetAttribute(gemmA<false>, cudaFuncAttributeMaxDynamicSharedMemorySize, GA_SMEM);
    cudaFuncSetAttribute(gemmA<true>,  cudaFuncAttributeMaxDynamicSharedMemorySize, GA_SMEM);
    cudaFuncSetAttribute(gemmB<false>, cudaFuncAttributeMaxDynamicSharedMemorySize, GB_SMEM);
    cudaFuncSetAttribute(gemmB<true>,  cudaFuncAttributeMaxDynamicSharedMemorySize, GB_SMEM);
    cudaFuncSetAttribute(gemmA_split,  cudaFuncAttributeMaxDynamicSharedMemorySize, GS_SMEM);

    // 0) prep: pre-round, hi/lo split, Vw transpose
    {
        RoundSegs rs;
        rs.s[0] = ly_w1;  rs.d[0] = p_w1r;  rs.n[0] = L_*4*D_*D_/4;
        rs.s[1] = ly_w2;  rs.d[1] = p_w2r;  rs.n[1] = L_*4*D_*D_/4;
        rs.s[2] = t_kw;   rs.d[2] = p_kvwr; rs.n[2] = D_*D_/4;
        rs.s[3] = t_vw;   rs.d[3] = p_kvwr + (size_t)D_*D_; rs.n[3] = D_*D_/4;
        rs.s[4] = proj_w; rs.d[4] = p_pwr;  rs.n[4] = HLLM_*D_/4;
        rs.s[5] = ly_ow;  rs.d[5] = p_owr;  rs.n[5] = 2*D_*D_/4;
        rs.s[6] = mem_q;  rs.d[6] = p_qr;   rs.n[6] = M_*D_/4;
        rs.s[7] = t_qw;   rs.d[7] = p_qwr;  rs.n[7] = D_*D_/4;
        rs.s[8] = t_ow;   rs.d[8] = p_towr; rs.n[8] = D_*D_/4;
        int total = 0;
        for (int k = 0; k < 9; k++) total += rs.n[k];
        round_allN<<<(total + 255)/256, 256>>>(rs);
        round_split2<<<((R_*RD_ + D_*RD_)/4 + 255)/256, 256>>>(
            rel_emb, p_ehi, p_elo, R_*RD_/4,
            rp_w,    p_whi, p_wlo, D_*RD_/4);
        transpose_round<<<dim3(16,16,2), 256>>>(ly_vw, p_vwT);
    }

    // 1) relation table projection (split-tf32, async)
    gemmA_split<<<g64(R_, D_), 128, GS_SMEM>>>(p_ehi, p_elo, p_whi, p_wlo,
                                               rp_b, p_relproj, R_, D_, RD_);
    rownorm_kernel<<<R_/8, 256>>>();

    // 2) compose out_l∘v_l
    gemmA<false><<<g64(D_, D_, 2), 128, GA_SMEM>>>(
        p_owr, p_owr + (size_t)D_*D_,
        p_vwT, p_zero, p_wc,
        p_vwT + (size_t)D_*D_, p_zero, p_wc + (size_t)D_*D_,
        D_, D_, D_, 2, 1);
    bias_combine<<<128, 256>>>(ly_ow, ly_vb, ly_ob);

    // 3) sims / top-8 / agg
    sims_topk_agg<<<BE_, 256>>>(edge_rel_ids, neigh_ids);

    // 4) attention branch (128-row tile)
    gemmB<false><<<g128(BE_, D_, 2), 256, GB_SMEM>>>(
        p_agg, p_agg,
        p_wc, p_bc, p_attn0,
        p_wc + (size_t)D_*D_, p_bc + D_, p_attn1,
        BE_, D_, D_, 0, 1);

    // 5) relation-context layers
    for (int l = 0; l < L_; l++) {
        const float* w1r = p_w1r + (size_t)l * 4 * D_ * D_;
        const float* b1  = ly_b1 + (size_t)l * 4 * D_;
        const float* w2r = p_w2r + (size_t)l * D_ * 4 * D_;
        const float* b2  = ly_b2 + (size_t)l * D_;
        const float* attn = l ? p_attn1 : p_attn0;

        add_ln_kernel<false><<<BE_, 256>>>(attn, nullptr,
                                           ly_n1g + (size_t)l*D_, ly_n1b + (size_t)l*D_, nullptr);
        gemmB<false><<<g128(BE_, 4*D_), 256, GB_SMEM>>>(p_states, p_states, w1r, b1, p_h,
                                                        w1r, b1, p_h, BE_, 4*D_, D_, 1, 1);
        gemmB<true><<<g128(BE_, D_, KS_), 256, GB_SMEM>>>(p_h, p_h, w2r, nullptr, p_part,
                                                          nullptr, nullptr, nullptr,
                                                          BE_, D_, 4*D_, 0, KS_);
        add_ln_kernel<true><<<BE_, 256>>>(nullptr, b2,
                                          ly_n2g + (size_t)l*D_, ly_n2b + (size_t)l*D_, edge_mask);
    }

    // 6) memory tokenizer
    gemmA<false><<<g64(M_, D_), 128, GA_SMEM>>>(p_qr, p_qr, p_qwr, t_qb, p_q,
                                                p_qwr, t_qb, p_q, M_, D_, D_, 0, 1);
    gemmB<false><<<g128(BE_, D_, 2), 256, GB_SMEM>>>(p_states, p_states,
                                                     p_kvwr, t_kb, p_k,
                                                     p_kvwr + (size_t)D_*D_, t_vb, p_v,
                                                     BE_, D_, D_, 0, 1);
    mem_attn2<<<B_*HEADS_, 256>>>(edge_mask);
    gemmA<false><<<g64(BM_, D_), 128, GA_SMEM>>>(p_mem, p_mem, p_towr, t_ob, p_memo,
                                                 p_towr, t_ob, p_memo, BM_, D_, D_, 2, 1);
    noedge_flags<<<B_, 256>>>(edge_mask);
    apply_noedge<<<(BM_*D_)/256, 256>>>();

    // 7) final projection
    gemmA<false><<<g64(BM_, HLLM_), 128, GA_SMEM>>>(p_memo, p_memo, p_pwr, proj_b, out,
                                                    p_pwr, proj_b, out, BM_, HLLM_, D_, 0, 1);
}

// round 15
// speedup vs baseline: 1.0489x; 1.0489x over previous
#include <cuda_runtime.h>
#include <cuda_bf16.h>
#include <cstdint>
#include <math.h>
#include <float.h>

// ---------------- problem constants ----------------
#define B_   8
#define E_   256
#define N_   32
#define D_   512
#define RD_  768
#define R_   2000
#define L_   2
#define K_   8
#define M_   32
#define HEADS_ 8
#define DH_  64
#define HLLM_ 4096
#define BE_  (B_*E_)      // 2048
#define BM_  (B_*M_)      // 256
#define KS_  4            // split-K factor for w2

#define GA_STRIDE 36
#define GA_SMEM   (3*64*GA_STRIDE*4*2)          // 55296 B  (gemmA 64x64, 3-stage)
#define GS_SMEM   (2*4*64*GA_STRIDE*4)          // 73728 B  (gemmA_split)

// ---------------- scratch ----------------
__device__ float g_relproj[R_*D_];
__device__ float g_inorm[R_];
__device__ float g_states[BE_*D_];
__device__ float g_agg[BE_*D_];
__device__ float g_attn0[BE_*D_];
__device__ float g_attn1[BE_*D_];
__device__ float g_h[BE_*4*D_];
__device__ float g_part[KS_*BE_*D_];
__device__ float g_wc[2*D_*D_];
__device__ float g_bc[2*D_];
__device__ float g_zero[D_];
__device__ float g_q[M_*D_];
__device__ float g_k[BE_*D_];
__device__ float g_v[BE_*D_];
__device__ float g_mem[BM_*D_];
__device__ float g_memo[BM_*D_];
__device__ float g_noedge[B_];
__device__ float g_w1r[(size_t)L_*4*D_*D_];
__device__ float g_w2r[(size_t)L_*4*D_*D_];
__device__ float g_kvwr[2*D_*D_];
__device__ float g_pwr[(size_t)HLLM_*D_];
__device__ float g_owr[2*D_*D_];
__device__ float g_vwT[2*D_*D_];
__device__ float g_qr[M_*D_];
__device__ float g_qwr[D_*D_];
__device__ float g_towr[D_*D_];
__device__ float g_ehi[(size_t)R_*RD_];
__device__ float g_elo[(size_t)R_*RD_];
__device__ float g_whi[(size_t)D_*RD_];
__device__ float g_wlo[(size_t)D_*RD_];

// ---------------- tf32 helpers ----------------
__device__ __forceinline__ unsigned f2tf32(float f) {
    unsigned u;
    asm("cvt.rna.tf32.f32 %0, %1;" : "=r"(u) : "f"(f));
    return u;
}
__device__ __forceinline__ float rtf(float f) { return __uint_as_float(f2tf32(f)); }
__device__ __forceinline__ void mma_tf32(float c[4], const unsigned a[4], const unsigned b[2]) {
    asm volatile(
        "mma.sync.aligned.m16n8k8.row.col.f32.tf32.tf32.f32 "
        "{%0,%1,%2,%3}, {%4,%5,%6,%7}, {%8,%9}, {%0,%1,%2,%3};"
        : "+f"(c[0]), "+f"(c[1]), "+f"(c[2]), "+f"(c[3])
        : "r"(a[0]), "r"(a[1]), "r"(a[2]), "r"(a[3]), "r"(b[0]), "r"(b[1]));
}
__device__ __forceinline__ void cp16(unsigned int saddr, const float* gaddr, int sz) {
    asm volatile("cp.async.cg.shared.global [%0], [%1], 16, %2;"
                 :: "r"(saddr), "l"(gaddr), "r"(sz));
}

// ---------------- merged 9-segment tf32 pre-round ----------------
struct RoundSegs {
    const float* s[9];
    float* d[9];
    int n[9];
};
__global__ void round_allN(RoundSegs seg)
{
    int i = blockIdx.x * 256 + threadIdx.x;
    #pragma unroll
    for (int k = 0; k < 9; k++) {
        if (i < seg.n[k]) {
            float4 v = *(const float4*)&seg.s[k][(size_t)i * 4];
            v.x = rtf(v.x); v.y = rtf(v.y); v.z = rtf(v.z); v.w = rtf(v.w);
            *(float4*)&seg.d[k][(size_t)i * 4] = v;
            return;
        }
        i -= seg.n[k];
    }
}

// ---------------- hi/lo split prep ----------------
__global__ void round_split2(const float* __restrict__ s0, float* __restrict__ h0,
                             float* __restrict__ l0, int n0,
                             const float* __restrict__ s1, float* __restrict__ h1,
                             float* __restrict__ l1, int n1)
{
    int i = blockIdx.x * 256 + threadIdx.x;
    const float* s; float *h, *l;
    if (i < n0) { s = s0; h = h0; l = l0; }
    else if ((i -= n0) < n1) { s = s1; h = h1; l = l1; }
    else return;
    float4 v = *(const float4*)&s[(size_t)i * 4];
    float4 hv, lv;
    hv.x = rtf(v.x); lv.x = rtf(v.x - hv.x);
    hv.y = rtf(v.y); lv.y = rtf(v.y - hv.y);
    hv.z = rtf(v.z); lv.z = rtf(v.z - hv.z);
    hv.w = rtf(v.w); lv.w = rtf(v.w - hv.w);
    *(float4*)&h[(size_t)i * 4] = hv;
    *(float4*)&l[(size_t)i * 4] = lv;
}

// ---------------- transpose + round ----------------
__global__ void transpose_round(const float* __restrict__ src, float* __restrict__ dst)
{
    __shared__ float tile[32][33];
    int l  = blockIdx.z;
    int i0 = blockIdx.y * 32, j0 = blockIdx.x * 32;
    int tx = threadIdx.x & 31, ty = threadIdx.x >> 5;
    #pragma unroll
    for (int r = ty; r < 32; r += 8)
        tile[r][tx] = src[(size_t)l*D_*D_ + (size_t)(i0+r)*D_ + j0+tx];
    __syncthreads();
    #pragma unroll
    for (int r = ty; r < 32; r += 8)
        dst[(size_t)l*D_*D_ + (size_t)(j0+r)*D_ + i0+tx] = rtf(tile[tx][r]);
}

// ---------------- cp.async tf32 NT GEMM, 64x64, BK=32, 3-stage ----------------
template<bool SK>
__global__ __launch_bounds__(128) void gemmA(
    const float* __restrict__ A0, const float* __restrict__ A1,
    const float* __restrict__ W0, const float* __restrict__ bias0, float* __restrict__ C0,
    const float* __restrict__ W1, const float* __restrict__ bias1, float* __restrict__ C1,
    int Mr, int Nc, int Kd, int act, int nsplit)
{
    extern __shared__ float dsm[];
    float (*As)[GA_STRIDE] = (float(*)[GA_STRIDE])dsm;
    float (*Ws)[GA_STRIDE] = (float(*)[GA_STRIDE])(dsm + 3*64*GA_STRIDE);

    const float* A;
    const float* W;
    const float* bias;
    float* C;
    int kbase = 0, nIter;
    if (SK) {
        A = A0; W = W0; bias = bias0;
        const int Kc = Kd / nsplit;
        kbase = blockIdx.z * Kc;
        nIter = Kc / 32;
        C = C0 + (size_t)blockIdx.z * Mr * Nc;
    } else {
        A    = blockIdx.z ? A1 : A0;
        W    = blockIdx.z ? W1 : W0;
        bias = blockIdx.z ? bias1 : bias0;
        C    = blockIdx.z ? C1 : C0;
        nIter = Kd / 32;
    }

    const int tid  = threadIdx.x;
    const int warp = tid >> 5, lane = tid & 31;
    const int wy   = warp >> 1, wx = warp & 1;
    const int grp  = lane >> 2, tig = lane & 3;
    const int row0 = blockIdx.y * 64;
    const int col0 = blockIdx.x * 64;
    const int lr   = tid >> 3;
    const int lk   = (tid & 7) * 4;

    const unsigned int sA = (unsigned int)__cvta_generic_to_shared(dsm);
    const unsigned int sW = (unsigned int)__cvta_generic_to_shared(dsm + 3*64*GA_STRIDE);
    const int v0s = (row0 + lr      < Mr) ? 16 : 0;
    const int v1s = (row0 + lr + 16 < Mr) ? 16 : 0;
    const int v2s = (row0 + lr + 32 < Mr) ? 16 : 0;
    const int v3s = (row0 + lr + 48 < Mr) ? 16 : 0;

    float acc[2][4][4] = {};

    #define ISSUE(st, itv)                                                              \
    {                                                                                   \
        const int k0 = kbase + (itv) * 32;                                              \
        cp16(sA + (((st)*64 + lr     )*GA_STRIDE + lk)*4, &A[(size_t)(row0+lr   ) * Kd + k0 + lk], v0s); \
        cp16(sA + (((st)*64 + lr + 16)*GA_STRIDE + lk)*4, &A[(size_t)(row0+lr+16) * Kd + k0 + lk], v1s); \
        cp16(sA + (((st)*64 + lr + 32)*GA_STRIDE + lk)*4, &A[(size_t)(row0+lr+32) * Kd + k0 + lk], v2s); \
        cp16(sA + (((st)*64 + lr + 48)*GA_STRIDE + lk)*4, &A[(size_t)(row0+lr+48) * Kd + k0 + lk], v3s); \
        cp16(sW + (((st)*64 + lr     )*GA_STRIDE + lk)*4, &W[(size_t)(col0+lr   ) * Kd + k0 + lk], 16); \
        cp16(sW + (((st)*64 + lr + 16)*GA_STRIDE + lk)*4, &W[(size_t)(col0+lr+16) * Kd + k0 + lk], 16); \
        cp16(sW + (((st)*64 + lr + 32)*GA_STRIDE + lk)*4, &W[(size_t)(col0+lr+32) * Kd + k0 + lk], 16); \
        cp16(sW + (((st)*64 + lr + 48)*GA_STRIDE + lk)*4, &W[(size_t)(col0+lr+48) * Kd + k0 + lk], 16); \
    }

    ISSUE(0, 0);
    asm volatile("cp.async.commit_group;");
    if (nIter > 1) ISSUE(1, 1);
    asm volatile("cp.async.commit_group;");

    for (int it = 0; it < nIter; it++) {
        asm volatile("cp.async.wait_group 1;");
        __syncthreads();

        if (it + 2 < nIter) ISSUE((it + 2) % 3, it + 2);
        asm volatile("cp.async.commit_group;");

        const int buf = it % 3;
        #pragma unroll
        for (int ks = 0; ks < 4; ks++) {
            const int kb = ks * 8;
            unsigned aH[2][4], bH[4][2];
            #pragma unroll
            for (int mt = 0; mt < 2; mt++) {
                const int mr = buf * 64 + wy * 32 + mt * 16 + grp;
                aH[mt][0] = __float_as_uint(As[mr    ][kb + tig]);
                aH[mt][1] = __float_as_uint(As[mr + 8][kb + tig]);
                aH[mt][2] = __float_as_uint(As[mr    ][kb + tig + 4]);
                aH[mt][3] = __float_as_uint(As[mr + 8][kb + tig + 4]);
            }
            #pragma unroll
            for (int nt = 0; nt < 4; nt++) {
                const int nc = buf * 64 + wx * 32 + nt * 8 + grp;
                bH[nt][0] = __float_as_uint(Ws[nc][kb + tig]);
                bH[nt][1] = __float_as_uint(Ws[nc][kb + tig + 4]);
            }
            #pragma unroll
            for (int mt = 0; mt < 2; mt++)
                #pragma unroll
                for (int nt = 0; nt < 4; nt++)
                    mma_tf32(acc[mt][nt], aH[mt], bH[nt]);
        }
        __syncthreads();
    }
    #undef ISSUE

    #pragma unroll
    for (int mt = 0; mt < 2; mt++) {
        const int r0 = row0 + wy * 32 + mt * 16 + grp;
        const int r1 = r0 + 8;
        #pragma unroll
        for (int nt = 0; nt < 4; nt++) {
            const int gc = col0 + wx * 32 + nt * 8 + tig * 2;
            float v0 = acc[mt][nt][0], v1 = acc[mt][nt][1];
            float v2 = acc[mt][nt][2], v3 = acc[mt][nt][3];
            if (!SK) {
                const float b0 = bias[gc], b1 = bias[gc + 1];
                v0 += b0; v1 += b1; v2 += b0; v3 += b1;
                if (act == 1) {
                    v0 = rtf(0.5f * v0 * (1.f + erff(v0 * 0.70710678118654752f)));
                    v1 = rtf(0.5f * v1 * (1.f + erff(v1 * 0.70710678118654752f)));
                    v2 = rtf(0.5f * v2 * (1.f + erff(v2 * 0.70710678118654752f)));
                    v3 = rtf(0.5f * v3 * (1.f + erff(v3 * 0.70710678118654752f)));
                } else if (act == 2) {
                    v0 = rtf(v0); v1 = rtf(v1); v2 = rtf(v2); v3 = rtf(v3);
                }
            }
            if (r0 < Mr) *(float2*)&C[(size_t)r0 * Nc + gc] = make_float2(v0, v1);
            if (r1 < Mr) *(float2*)&C[(size_t)r1 * Nc + gc] = make_float2(v2, v3);
        }
    }
}

// ---------------- cp.async split-tf32 GEMM (relproj) ----------------
__global__ __launch_bounds__(128) void gemmA_split(
    const float* __restrict__ Ahi, const float* __restrict__ Alo,
    const float* __restrict__ Whi, const float* __restrict__ Wlo,
    const float* __restrict__ bias, float* __restrict__ C,
    int Mr, int Nc, int Kd)
{
    extern __shared__ float dsm[];
    float (*SM)[GA_STRIDE] = (float(*)[GA_STRIDE])dsm;

    const int tid  = threadIdx.x;
    const int warp = tid >> 5, lane = tid & 31;
    const int wy   = warp >> 1, wx = warp & 1;
    const int grp  = lane >> 2, tig = lane & 3;
    const int row0 = blockIdx.y * 64;
    const int col0 = blockIdx.x * 64;
    const int lr   = tid >> 3;
    const int lk   = (tid & 7) * 4;

    const unsigned int sB = (unsigned int)__cvta_generic_to_shared(dsm);
    const int v0s = (row0 + lr      < Mr) ? 16 : 0;
    const int v1s = (row0 + lr + 16 < Mr) ? 16 : 0;
    const int v2s = (row0 + lr + 32 < Mr) ? 16 : 0;
    const int v3s = (row0 + lr + 48 < Mr) ? 16 : 0;

    const int nIter = Kd / 32;
    float acc[2][4][4] = {};

    #define SISSUE(st, itv)                                                             \
    {                                                                                   \
        const int k0 = (itv) * 32;                                                      \
        const int sb = (st) * 256;                                                      \
        cp16(sB + ((sb       + lr     )*GA_STRIDE + lk)*4, &Ahi[(size_t)(row0+lr   ) * Kd + k0 + lk], v0s); \
        cp16(sB + ((sb       + lr + 16)*GA_STRIDE + lk)*4, &Ahi[(size_t)(row0+lr+16) * Kd + k0 + lk], v1s); \
        cp16(sB + ((sb       + lr + 32)*GA_STRIDE + lk)*4, &Ahi[(size_t)(row0+lr+32) * Kd + k0 + lk], v2s); \
        cp16(sB + ((sb       + lr + 48)*GA_STRIDE + lk)*4, &Ahi[(size_t)(row0+lr+48) * Kd + k0 + lk], v3s); \
        cp16(sB + ((sb + 64  + lr     )*GA_STRIDE + lk)*4, &Alo[(size_t)(row0+lr   ) * Kd + k0 + lk], v0s); \
        cp16(sB + ((sb + 64  + lr + 16)*GA_STRIDE + lk)*4, &Alo[(size_t)(row0+lr+16) * Kd + k0 + lk], v1s); \
        cp16(sB + ((sb + 64  + lr + 32)*GA_STRIDE + lk)*4, &Alo[(size_t)(row0+lr+32) * Kd + k0 + lk], v2s); \
        cp16(sB + ((sb + 64  + lr + 48)*GA_STRIDE + lk)*4, &Alo[(size_t)(row0+lr+48) * Kd + k0 + lk], v3s); \
        cp16(sB + ((sb + 128 + lr     )*GA_STRIDE + lk)*4, &Whi[(size_t)(col0+lr   ) * Kd + k0 + lk], 16); \
        cp16(sB + ((sb + 128 + lr + 16)*GA_STRIDE + lk)*4, &Whi[(size_t)(col0+lr+16) * Kd + k0 + lk], 16); \
        cp16(sB + ((sb + 128 + lr + 32)*GA_STRIDE + lk)*4, &Whi[(size_t)(col0+lr+32) * Kd + k0 + lk], 16); \
        cp16(sB + ((sb + 128 + lr + 48)*GA_STRIDE + lk)*4, &Whi[(size_t)(col0+lr+48) * Kd + k0 + lk], 16); \
        cp16(sB + ((sb + 192 + lr     )*GA_STRIDE + lk)*4, &Wlo[(size_t)(col0+lr   ) * Kd + k0 + lk], 16); \
        cp16(sB + ((sb + 192 + lr + 16)*GA_STRIDE + lk)*4, &Wlo[(size_t)(col0+lr+16) * Kd + k0 + lk], 16); \
        cp16(sB + ((sb + 192 + lr + 32)*GA_STRIDE + lk)*4, &Wlo[(size_t)(col0+lr+32) * Kd + k0 + lk], 16); \
        cp16(sB + ((sb + 192 + lr + 48)*GA_STRIDE + lk)*4, &Wlo[(size_t)(col0+lr+48) * Kd + k0 + lk], 16); \
    }

    SISSUE(0, 0);
    asm volatile("cp.async.commit_group;");

    for (int it = 0; it < nIter; it++) {
        if (it + 1 < nIter) SISSUE((it + 1) & 1, it + 1);
        asm volatile("cp.async.commit_group;");
        asm volatile("cp.async.wait_group 1;");
        __syncthreads();

        const int sb = (it & 1) * 256;
        #pragma unroll
        for (int ks = 0; ks < 4; ks++) {
            const int kb = ks * 8;
            unsigned aH[2][4], aL[2][4], bH[4][2], bL[4][2];
            #pragma unroll
            for (int mt = 0; mt < 2; mt++) {
                const int mr = sb + wy * 32 + mt * 16 + grp;
                aH[mt][0] = __float_as_uint(SM[mr    ][kb + tig]);
                aH[mt][1] = __float_as_uint(SM[mr + 8][kb + tig]);
                aH[mt][2] = __float_as_uint(SM[mr    ][kb + tig + 4]);
                aH[mt][3] = __float_as_uint(SM[mr + 8][kb + tig + 4]);
                aL[mt][0] = __float_as_uint(SM[mr + 64    ][kb + tig]);
                aL[mt][1] = __float_as_uint(SM[mr + 64 + 8][kb + tig]);
                aL[mt][2] = __float_as_uint(SM[mr + 64    ][kb + tig + 4]);
                aL[mt][3] = __float_as_uint(SM[mr + 64 + 8][kb + tig + 4]);
            }
            #pragma unroll
            for (int nt = 0; nt < 4; nt++) {
                const int nc = sb + 128 + wx * 32 + nt * 8 + grp;
                bH[nt][0] = __float_as_uint(SM[nc][kb + tig]);
                bH[nt][1] = __float_as_uint(SM[nc][kb + tig + 4]);
                bL[nt][0] = __float_as_uint(SM[nc + 64][kb + tig]);
                bL[nt][1] = __float_as_uint(SM[nc + 64][kb + tig + 4]);
            }
            #pragma unroll
            for (int mt = 0; mt < 2; mt++)
                #pragma unroll
                for (int nt = 0; nt < 4; nt++) {
                    mma_tf32(acc[mt][nt], aH[mt], bH[nt]);
                    mma_tf32(acc[mt][nt], aH[mt], bL[nt]);
                    mma_tf32(acc[mt][nt], aL[mt], bH[nt]);
                }
        }
        __syncthreads();
    }
    #undef SISSUE

    #pragma unroll
    for (int mt = 0; mt < 2; mt++) {
        const int r0 = row0 + wy * 32 + mt * 16 + grp;
        const int r1 = r0 + 8;
        #pragma unroll
        for (int nt = 0; nt < 4; nt++) {
            const int gc = col0 + wx * 32 + nt * 8 + tig * 2;
            const float b0 = bias[gc], b1 = bias[gc + 1];
            if (r0 < Mr) *(float2*)&C[(size_t)r0 * Nc + gc] =
                make_float2(acc[mt][nt][0] + b0, acc[mt][nt][1] + b1);
            if (r1 < Mr) *(float2*)&C[(size_t)r1 * Nc + gc] =
                make_float2(acc[mt][nt][2] + b0, acc[mt][nt][3] + b1);
        }
    }
}

// ---------------- composed bias ----------------
__global__ void bias_combine(const float* __restrict__ ly_ow,
                             const float* __restrict__ ly_vb,
                             const float* __restrict__ ly_ob)
{
    int gw = blockIdx.x * 8 + (threadIdx.x >> 5);
    int lane = threadIdx.x & 31;
    int l = gw >> 9, row = gw & 511;
    const float* Ow = ly_ow + (size_t)l * D_ * D_ + (size_t)row * D_;
    const float* vb = ly_vb + (size_t)l * D_;
    float s = 0.f;
    #pragma unroll
    for (int k = 0; k < 4; k++) {
        int idx = (k * 32 + lane) * 4;
        float4 a = *(const float4*)&Ow[idx];
        float4 v = *(const float4*)&vb[idx];
        s += a.x * v.x + a.y * v.y + a.z * v.z + a.w * v.w;
    }
    #pragma unroll
    for (int o = 16; o; o >>= 1) s += __shfl_down_sync(0xffffffffu, s, o);
    if (lane == 0) g_bc[l * D_ + row] = s + ly_ob[l * D_ + row];
}

// ---------------- per-row inverse norm (warp per row) ----------------
__global__ void rownorm_kernel()
{
    int r = blockIdx.x * 8 + (threadIdx.x >> 5);
    int lane = threadIdx.x & 31;
    const float* row = &g_relproj[(size_t)r * D_];
    float s = 0.f;
    #pragma unroll
    for (int k = 0; k < 4; k++) {
        float4 v = *(const float4*)&row[(k * 32 + lane) * 4];
        s += v.x*v.x + v.y*v.y + v.z*v.z + v.w*v.w;
    }
    #pragma unroll
    for (int o = 16; o; o >>= 1) s += __shfl_down_sync(0xffffffffu, s, o);
    if (lane == 0) g_inorm[r] = 1.f / fmaxf(sqrtf(s), 1e-12f);
}

// ---------------- fused sims / top-8 / mean agg ----------------
__global__ void sims_topk_agg(const int* __restrict__ eids, const int* __restrict__ nids)
{
    int be = blockIdx.x;
    __shared__ float rn[D_];
    __shared__ float sims[N_];
    __shared__ int   topid[K_];

    int eid = eids[be];
    float ei = g_inorm[eid];
    for (int d = threadIdx.x; d < D_; d += 256) {
        float v = g_relproj[(size_t)eid * D_ + d];
        g_states[(size_t)be * D_ + d] = rtf(v);
        rn[d] = v * ei;
    }
    __syncthreads();

    int warp = threadIdx.x >> 5, lane = threadIdx.x & 31;
    for (int n = warp; n < N_; n += 8) {
        int nid = nids[(size_t)be * N_ + n];
        const float* row = &g_relproj[(size_t)nid * D_];
        float s = 0.f;
        for (int d = lane; d < D_; d += 32) s += row[d] * rn[d];
        #pragma unroll
        for (int o = 16; o; o >>= 1) s += __shfl_down_sync(0xffffffffu, s, o);
        if (lane == 0) sims[n] = s * g_inorm[nid];
    }
    __syncthreads();

    if (threadIdx.x == 0) {
        unsigned used = 0;
        for (int j = 0; j < K_; j++) {
            float best = -FLT_MAX; int bi = 0;
            for (int n = 0; n < N_; n++) {
                if ((used >> n) & 1u) continue;
                if (sims[n] > best) { best = sims[n]; bi = n; }
            }
            used |= 1u << bi;
            topid[j] = nids[(size_t)be * N_ + bi];
        }
    }
    __syncthreads();

    for (int d = threadIdx.x; d < D_; d += 256) {
        float acc = 0.f;
        #pragma unroll
        for (int j = 0; j < K_; j++) acc += g_relproj[(size_t)topid[j] * D_ + d];
        g_agg[(size_t)be * D_ + d] = rtf(acc * (1.f / K_));
    }
}

// ---------------- residual + layernorm; warp-shuffle reductions ----------
template<bool SKMODE>
__global__ void add_ln_kernel(const float* __restrict__ addp,
                              const float* __restrict__ bias,
                              const float* __restrict__ gamma, const float* __restrict__ beta,
                              const float* __restrict__ mask)
{
    int r = blockIdx.x;
    int t = threadIdx.x;
    const int warp = t >> 5, lane = t & 31;
    __shared__ float pw[8];
    __shared__ float bc;

    float a0, a1;
    if (SKMODE) {
        size_t o0 = (size_t)r*D_ + t, o1 = o0 + 256;
        a0 = g_part[o0] + g_part[(size_t)BE_*D_ + o0] + g_part[2*(size_t)BE_*D_ + o0]
           + g_part[3*(size_t)BE_*D_ + o0] + bias[t];
        a1 = g_part[o1] + g_part[(size_t)BE_*D_ + o1] + g_part[2*(size_t)BE_*D_ + o1]
           + g_part[3*(size_t)BE_*D_ + o1] + bias[t + 256];
    } else {
        a0 = addp[(size_t)r*D_ + t];
        a1 = addp[(size_t)r*D_ + t + 256];
    }
    float x0 = g_states[(size_t)r*D_ + t]       + a0;
    float x1 = g_states[(size_t)r*D_ + t + 256] + a1;

    // mean
    float s = x0 + x1;
    #pragma unroll
    for (int o = 16; o; o >>= 1) s += __shfl_xor_sync(0xffffffffu, s, o);
    if (lane == 0) pw[warp] = s;
    __syncthreads();
    if (warp == 0) {
        float v = (lane < 8) ? pw[lane] : 0.f;
        #pragma unroll
        for (int o = 4; o; o >>= 1) v += __shfl_xor_sync(0xffffffffu, v, o);
        if (lane == 0) bc = v * (1.f / D_);
    }
    __syncthreads();
    float mu = bc;

    // variance
    float d0 = x0 - mu, d1 = x1 - mu;
    s = d0*d0 + d1*d1;
    #pragma unroll
    for (int o = 16; o; o >>= 1) s += __shfl_xor_sync(0xffffffffu, s, o);
    if (lane == 0) pw[warp] = s;
    __syncthreads();
    if (warp == 0) {
        float v = (lane < 8) ? pw[lane] : 0.f;
        #pragma unroll
        for (int o = 4; o; o >>= 1) v += __shfl_xor_sync(0xffffffffu, v, o);
        if (lane == 0) bc = rsqrtf(v * (1.f / D_) + 1e-5f);
    }
    __syncthreads();
    float inv = bc;

    float mf = mask ? mask[r] : 1.f;
    g_states[(size_t)r*D_ + t]       = rtf((d0 * inv * gamma[t]     + beta[t])     * mf);
    g_states[(size_t)r*D_ + t + 256] = rtf((d1 * inv * gamma[t+256] + beta[t+256]) * mf);
}

// ---------------- memory-token cross attention ----------------
#define ETILE 16
__global__ __launch_bounds__(256) void mem_attn2(const float* __restrict__ edge_mask)
{
    const int b = blockIdx.x >> 3;
    const int h = blockIdx.x & 7;
    const int tid = threadIdx.x;

    __shared__ float Qs[M_][DH_ + 1];
    __shared__ float S[M_][E_];
    __shared__ float KV[ETILE][DH_ + 1];

    for (int i = tid; i < M_ * DH_; i += 256) {
        int m = i >> 6, d = i & 63;
        Qs[m][d] = g_q[(size_t)m * D_ + h * DH_ + d];
    }

    const float* mk = &edge_mask[(size_t)b * E_];
    const float* kb = &g_k[(size_t)b * E_ * D_ + h * DH_];
    const float* vb = &g_v[(size_t)b * E_ * D_ + h * DH_];
    __syncthreads();

    for (int et = 0; et < E_ / ETILE; et++) {
        for (int i = tid; i < ETILE * DH_; i += 256) {
            int e = i >> 6, d = i & 63;
            KV[e][d] = kb[(size_t)(et * ETILE + e) * D_ + d];
        }
        __syncthreads();
        #pragma unroll
        for (int p = 0; p < 2; p++) {
            int idx = tid * 2 + p;
            int m = idx >> 4, e = idx & 15;
            float s = 0.f;
            #pragma unroll 8
            for (int d = 0; d < DH_; d++) s += Qs[m][d] * KV[e][d];
            int eg = et * ETILE + e;
            S[m][eg] = (mk[eg] == 0.f) ? -FLT_MAX : s * 0.125f;
        }
        __syncthreads();
    }

    {
        const int warp = tid >> 5, lane = tid & 31;
        for (int r = 0; r < 4; r++) {
            const int m = warp * 4 + r;
            float mx = -FLT_MAX;
            for (int e = lane; e < E_; e += 32) mx = fmaxf(mx, S[m][e]);
            #pragma unroll
            for (int o = 16; o; o >>= 1) mx = fmaxf(mx, __shfl_xor_sync(0xffffffffu, mx, o));
            float sum = 0.f;
            for (int e = lane; e < E_; e += 32) {
                float w = expf(S[m][e] - mx);
                S[m][e] = w;
                sum += w;
            }
            #pragma unroll
            for (int o = 16; o; o >>= 1) sum += __shfl_xor_sync(0xffffffffu, sum, o);
            float inv = 1.f / sum;
            for (int e = lane; e < E_; e += 32) S[m][e] *= inv;
        }
    }
    __syncthreads();

    const int m  = tid >> 3;
    const int d0 = (tid & 7) * 8;
    float acc[8] = {};
    for (int vt = 0; vt < E_ / ETILE; vt++) {
        for (int i = tid; i < ETILE * DH_; i += 256) {
            int e = i >> 6, d = i & 63;
            KV[e][d] = vb[(size_t)(vt * ETILE + e) * D_ + d];
        }
        __syncthreads();
        #pragma unroll
        for (int e = 0; e < ETILE; e++) {
            float w = S[m][vt * ETILE + e];
            #pragma unroll
            for (int j = 0; j < 8; j++) acc[j] += w * KV[e][d0 + j];
        }
        __syncthreads();
    }
    size_t o = (size_t)(b * M_ + m) * D_ + h * DH_ + d0;
    #pragma unroll
    for (int j = 0; j < 8; j++) g_mem[o + j] = rtf(acc[j]);
}

// ---------------- no-edge handling ----------------
__global__ void noedge_flags(const float* __restrict__ edge_mask)
{
    int b = blockIdx.x;
    __shared__ float red[256];
    red[threadIdx.x] = edge_mask[(size_t)b * E_ + threadIdx.x];
    __syncthreads();
    for (int s = 128; s; s >>= 1) { if (threadIdx.x < s) red[threadIdx.x] += red[threadIdx.x+s]; __syncthreads(); }
    if (threadIdx.x == 0) g_noedge[b] = (red[0] == 0.f) ? 0.f : 1.f;
}

__global__ void apply_noedge()
{
    int i = blockIdx.x * 256 + threadIdx.x;
    int b = i / (M_ * D_);
    g_memo[i] *= g_noedge[b];
}

// ---------------- host launch ----------------
static inline dim3 g64(int Mr, int Nc, int z = 1) {
    return dim3(Nc / 64, (Mr + 63) / 64, z);
}

extern "C" void kernel_launch(void* const* d_in, const int* in_sizes, int n_in,
                              void* d_out, int out_size)
{
    const int*   edge_rel_ids = (const int*)  d_in[0];
    const int*   neigh_ids    = (const int*)  d_in[1];
    const float* edge_mask    = (const float*)d_in[2];
    const float* rel_emb      = (const float*)d_in[3];
    const float* rp_w         = (const float*)d_in[4];
    const float* rp_b         = (const float*)d_in[5];
    const float* ly_vw        = (const float*)d_in[6];
    const float* ly_vb        = (const float*)d_in[7];
    const float* ly_ow        = (const float*)d_in[8];
    const float* ly_ob        = (const float*)d_in[9];
    const float* ly_n1g       = (const float*)d_in[10];
    const float* ly_n1b       = (const float*)d_in[11];
    const float* ly_n2g       = (const float*)d_in[12];
    const float* ly_n2b       = (const float*)d_in[13];
    const float* ly_w1        = (const float*)d_in[14];
    const float* ly_b1        = (const float*)d_in[15];
    const float* ly_w2        = (const float*)d_in[16];
    const float* ly_b2        = (const float*)d_in[17];
    const float* mem_q        = (const float*)d_in[18];
    const float* t_qw         = (const float*)d_in[19];
    const float* t_qb         = (const float*)d_in[20];
    const float* t_kw         = (const float*)d_in[21];
    const float* t_kb         = (const float*)d_in[22];
    const float* t_vw         = (const float*)d_in[23];
    const float* t_vb         = (const float*)d_in[24];
    const float* t_ow         = (const float*)d_in[25];
    const float* t_ob         = (const float*)d_in[26];
    const float* proj_w       = (const float*)d_in[27];
    const float* proj_b       = (const float*)d_in[28];
    float* out = (float*)d_out;

    float *p_relproj, *p_states, *p_agg, *p_attn0, *p_attn1, *p_h, *p_part;
    float *p_wc, *p_bc, *p_zero, *p_q, *p_k, *p_v, *p_mem, *p_memo;
    float *p_w1r, *p_w2r, *p_kvwr, *p_pwr, *p_owr, *p_vwT, *p_qr, *p_qwr, *p_towr;
    float *p_ehi, *p_elo, *p_whi, *p_wlo;
    cudaGetSymbolAddress((void**)&p_relproj, g_relproj);
    cudaGetSymbolAddress((void**)&p_states,  g_states);
    cudaGetSymbolAddress((void**)&p_agg,     g_agg);
    cudaGetSymbolAddress((void**)&p_attn0,   g_attn0);
    cudaGetSymbolAddress((void**)&p_attn1,   g_attn1);
    cudaGetSymbolAddress((void**)&p_h,       g_h);
    cudaGetSymbolAddress((void**)&p_part,    g_part);
    cudaGetSymbolAddress((void**)&p_wc,      g_wc);
    cudaGetSymbolAddress((void**)&p_bc,      g_bc);
    cudaGetSymbolAddress((void**)&p_zero,    g_zero);
    cudaGetSymbolAddress((void**)&p_q,       g_q);
    cudaGetSymbolAddress((void**)&p_k,       g_k);
    cudaGetSymbolAddress((void**)&p_v,       g_v);
    cudaGetSymbolAddress((void**)&p_mem,     g_mem);
    cudaGetSymbolAddress((void**)&p_memo,    g_memo);
    cudaGetSymbolAddress((void**)&p_w1r,     g_w1r);
    cudaGetSymbolAddress((void**)&p_w2r,     g_w2r);
    cudaGetSymbolAddress((void**)&p_kvwr,    g_kvwr);
    cudaGetSymbolAddress((void**)&p_pwr,     g_pwr);
    cudaGetSymbolAddress((void**)&p_owr,     g_owr);
    cudaGetSymbolAddress((void**)&p_vwT,     g_vwT);
    cudaGetSymbolAddress((void**)&p_qr,      g_qr);
    cudaGetSymbolAddress((void**)&p_qwr,     g_qwr);
    cudaGetSymbolAddress((void**)&p_towr,    g_towr);
    cudaGetSymbolAddress((void**)&p_ehi,     g_ehi);
    cudaGetSymbolAddress((void**)&p_elo,     g_elo);
    cudaGetSymbolAddress((void**)&p_whi,     g_whi);
    cudaGetSymbolAddress((void**)&p_wlo,     g_wlo);

    cudaFuncSetAttribute(gemmA<false>, cudaFuncAttributeMaxDynamicSharedMemorySize, GA_SMEM);
    cudaFuncSetAttribute(gemmA<true>,  cudaFuncAttributeMaxDynamicSharedMemorySize, GA_SMEM);
    cudaFuncSetAttribute(gemmA_split,  cudaFuncAttributeMaxDynamicSharedMemorySize, GS_SMEM);

    // 0) prep: pre-round, hi/lo split, Vw transpose
    {
        RoundSegs rs;
        rs.s[0] = ly_w1;  rs.d[0] = p_w1r;  rs.n[0] = L_*4*D_*D_/4;
        rs.s[1] = ly_w2;  rs.d[1] = p_w2r;  rs.n[1] = L_*4*D_*D_/4;
        rs.s[2] = t_kw;   rs.d[2] = p_kvwr; rs.n[2] = D_*D_/4;
        rs.s[3] = t_vw;   rs.d[3] = p_kvwr + (size_t)D_*D_; rs.n[3] = D_*D_/4;
        rs.s[4] = proj_w; rs.d[4] = p_pwr;  rs.n[4] = HLLM_*D_/4;
        rs.s[5] = ly_ow;  rs.d[5] = p_owr;  rs.n[5] = 2*D_*D_/4;
        rs.s[6] = mem_q;  rs.d[6] = p_qr;   rs.n[6] = M_*D_/4;
        rs.s[7] = t_qw;   rs.d[7] = p_qwr;  rs.n[7] = D_*D_/4;
        rs.s[8] = t_ow;   rs.d[8] = p_towr; rs.n[8] = D_*D_/4;
        int total = 0;
        for (int k = 0; k < 9; k++) total += rs.n[k];
        round_allN<<<(total + 255)/256, 256>>>(rs);
        round_split2<<<((R_*RD_ + D_*RD_)/4 + 255)/256, 256>>>(
            rel_emb, p_ehi, p_elo, R_*RD_/4,
            rp_w,    p_whi, p_wlo, D_*RD_/4);
        transpose_round<<<dim3(16,16,2), 256>>>(ly_vw, p_vwT);
    }

    // 1) relation table projection (split-tf32, async)
    gemmA_split<<<g64(R_, D_), 128, GS_SMEM>>>(p_ehi, p_elo, p_whi, p_wlo,
                                               rp_b, p_relproj, R_, D_, RD_);
    rownorm_kernel<<<R_/8, 256>>>();

    // 2) compose out_l∘v_l
    gemmA<false><<<g64(D_, D_, 2), 128, GA_SMEM>>>(
        p_owr, p_owr + (size_t)D_*D_,
        p_vwT, p_zero, p_wc,
        p_vwT + (size_t)D_*D_, p_zero, p_wc + (size_t)D_*D_,
        D_, D_, D_, 2, 1);
    bias_combine<<<128, 256>>>(ly_ow, ly_vb, ly_ob);

    // 3) sims / top-8 / agg
    sims_topk_agg<<<BE_, 256>>>(edge_rel_ids, neigh_ids);

    // 4) attention branch
    gemmA<false><<<g64(BE_, D_, 2), 128, GA_SMEM>>>(
        p_agg, p_agg,
        p_wc, p_bc, p_attn0,
        p_wc + (size_t)D_*D_, p_bc + D_, p_attn1,
        BE_, D_, D_, 0, 1);

    // 5) relation-context layers
    for (int l = 0; l < L_; l++) {
        const float* w1r = p_w1r + (size_t)l * 4 * D_ * D_;
        const float* b1  = ly_b1 + (size_t)l * 4 * D_;
        const float* w2r = p_w2r + (size_t)l * D_ * 4 * D_;
        const float* b2  = ly_b2 + (size_t)l * D_;
        const float* attn = l ? p_attn1 : p_attn0;

        add_ln_kernel<false><<<BE_, 256>>>(attn, nullptr,
                                           ly_n1g + (size_t)l*D_, ly_n1b + (size_t)l*D_, nullptr);
        gemmA<false><<<g64(BE_, 4*D_), 128, GA_SMEM>>>(p_states, p_states, w1r, b1, p_h,
                                                       w1r, b1, p_h, BE_, 4*D_, D_, 1, 1);
        gemmA<true><<<g64(BE_, D_, KS_), 128, GA_SMEM>>>(p_h, p_h, w2r, nullptr, p_part,
                                                         nullptr, nullptr, nullptr,
                                                         BE_, D_, 4*D_, 0, KS_);
        add_ln_kernel<true><<<BE_, 256>>>(nullptr, b2,
                                          ly_n2g + (size_t)l*D_, ly_n2b + (size_t)l*D_, edge_mask);
    }

    // 6) memory tokenizer
    gemmA<false><<<g64(M_, D_), 128, GA_SMEM>>>(p_qr, p_qr, p_qwr, t_qb, p_q,
                                                p_qwr, t_qb, p_q, M_, D_, D_, 0, 1);
    gemmA<false><<<g64(BE_, D_, 2), 128, GA_SMEM>>>(p_states, p_states,
                                                    p_kvwr, t_kb, p_k,
                                                    p_kvwr + (size_t)D_*D_, t_vb, p_v,
                                                    BE_, D_, D_, 0, 1);
    mem_attn2<<<B_*HEADS_, 256>>>(edge_mask);
    gemmA<false><<<g64(BM_, D_), 128, GA_SMEM>>>(p_mem, p_mem, p_towr, t_ob, p_memo,
                                                 p_towr, t_ob, p_memo, BM_, D_, D_, 2, 1);
    noedge_flags<<<B_, 256>>>(edge_mask);
    apply_noedge<<<(BM_*D_)/256, 256>>>();

    // 7) final projection
    gemmA<false><<<g64(BM_, HLLM_), 128, GA_SMEM>>>(p_memo, p_memo, p_pwr, proj_b, out,
                                                    p_pwr, proj_b, out, BM_, HLLM_, D_, 0, 1);
}

// round 16
// speedup vs baseline: 1.0588x; 1.0095x over previous
#include <cuda_runtime.h>
#include <cuda_bf16.h>
#include <cstdint>
#include <math.h>
#include <float.h>

// ---------------- problem constants ----------------
#define B_   8
#define E_   256
#define N_   32
#define D_   512
#define RD_  768
#define R_   2000
#define L_   2
#define K_   8
#define M_   32
#define HEADS_ 8
#define DH_  64
#define HLLM_ 4096
#define BE_  (B_*E_)      // 2048
#define BM_  (B_*M_)      // 256
#define KS_  4            // split-K factor for w2

#define GA_STRIDE 36
#define GA_SMEM   (3*64*GA_STRIDE*4*2)          // 55296 B  (gemmA 64x64, 3-stage)
#define GS_SMEM   (3*4*64*GA_STRIDE*4)          // 110592 B (gemmA_split, 3-stage, 4 streams)

// ---------------- scratch ----------------
__device__ float g_relproj[R_*D_];
__device__ float g_inorm[R_];
__device__ float g_states[BE_*D_];
__device__ float g_agg[BE_*D_];
__device__ float g_attn0[BE_*D_];
__device__ float g_attn1[BE_*D_];
__device__ float g_h[BE_*4*D_];
__device__ float g_part[KS_*BE_*D_];
__device__ float g_wc[2*D_*D_];
__device__ float g_bc[2*D_];
__device__ float g_zero[D_];
__device__ float g_q[M_*D_];
__device__ float g_k[BE_*D_];
__device__ float g_v[BE_*D_];
__device__ float g_mem[BM_*D_];
__device__ float g_memo[BM_*D_];
__device__ float g_noedge[B_];
__device__ float g_w1r[(size_t)L_*4*D_*D_];
__device__ float g_w2r[(size_t)L_*4*D_*D_];
__device__ float g_kvwr[2*D_*D_];
__device__ float g_pwr[(size_t)HLLM_*D_];
__device__ float g_owr[2*D_*D_];
__device__ float g_vwT[2*D_*D_];
__device__ float g_qr[M_*D_];
__device__ float g_qwr[D_*D_];
__device__ float g_towr[D_*D_];
__device__ float g_ehi[(size_t)R_*RD_];
__device__ float g_elo[(size_t)R_*RD_];
__device__ float g_whi[(size_t)D_*RD_];
__device__ float g_wlo[(size_t)D_*RD_];

// ---------------- tf32 helpers ----------------
__device__ __forceinline__ unsigned f2tf32(float f) {
    unsigned u;
    asm("cvt.rna.tf32.f32 %0, %1;" : "=r"(u) : "f"(f));
    return u;
}
__device__ __forceinline__ float rtf(float f) { return __uint_as_float(f2tf32(f)); }
__device__ __forceinline__ void mma_tf32(float c[4], const unsigned a[4], const unsigned b[2]) {
    asm volatile(
        "mma.sync.aligned.m16n8k8.row.col.f32.tf32.tf32.f32 "
        "{%0,%1,%2,%3}, {%4,%5,%6,%7}, {%8,%9}, {%0,%1,%2,%3};"
        : "+f"(c[0]), "+f"(c[1]), "+f"(c[2]), "+f"(c[3])
        : "r"(a[0]), "r"(a[1]), "r"(a[2]), "r"(a[3]), "r"(b[0]), "r"(b[1]));
}
__device__ __forceinline__ void cp16(unsigned int saddr, const float* gaddr, int sz) {
    asm volatile("cp.async.cg.shared.global [%0], [%1], 16, %2;"
                 :: "r"(saddr), "l"(gaddr), "r"(sz));
}

// ---------------- merged 9-segment tf32 pre-round ----------------
struct RoundSegs {
    const float* s[9];
    float* d[9];
    int n[9];
};
__global__ void round_allN(RoundSegs seg)
{
    int i = blockIdx.x * 256 + threadIdx.x;
    #pragma unroll
    for (int k = 0; k < 9; k++) {
        if (i < seg.n[k]) {
            float4 v = *(const float4*)&seg.s[k][(size_t)i * 4];
            v.x = rtf(v.x); v.y = rtf(v.y); v.z = rtf(v.z); v.w = rtf(v.w);
            *(float4*)&seg.d[k][(size_t)i * 4] = v;
            return;
        }
        i -= seg.n[k];
    }
}

// ---------------- hi/lo split prep ----------------
__global__ void round_split2(const float* __restrict__ s0, float* __restrict__ h0,
                             float* __restrict__ l0, int n0,
                             const float* __restrict__ s1, float* __restrict__ h1,
                             float* __restrict__ l1, int n1)
{
    int i = blockIdx.x * 256 + threadIdx.x;
    const float* s; float *h, *l;
    if (i < n0) { s = s0; h = h0; l = l0; }
    else if ((i -= n0) < n1) { s = s1; h = h1; l = l1; }
    else return;
    float4 v = *(const float4*)&s[(size_t)i * 4];
    float4 hv, lv;
    hv.x = rtf(v.x); lv.x = rtf(v.x - hv.x);
    hv.y = rtf(v.y); lv.y = rtf(v.y - hv.y);
    hv.z = rtf(v.z); lv.z = rtf(v.z - hv.z);
    hv.w = rtf(v.w); lv.w = rtf(v.w - hv.w);
    *(float4*)&h[(size_t)i * 4] = hv;
    *(float4*)&l[(size_t)i * 4] = lv;
}

// ---------------- transpose + round ----------------
__global__ void transpose_round(const float* __restrict__ src, float* __restrict__ dst)
{
    __shared__ float tile[32][33];
    int l  = blockIdx.z;
    int i0 = blockIdx.y * 32, j0 = blockIdx.x * 32;
    int tx = threadIdx.x & 31, ty = threadIdx.x >> 5;
    #pragma unroll
    for (int r = ty; r < 32; r += 8)
        tile[r][tx] = src[(size_t)l*D_*D_ + (size_t)(i0+r)*D_ + j0+tx];
    __syncthreads();
    #pragma unroll
    for (int r = ty; r < 32; r += 8)
        dst[(size_t)l*D_*D_ + (size_t)(j0+r)*D_ + i0+tx] = rtf(tile[tx][r]);
}

// ---------------- cp.async tf32 NT GEMM, 64x64, BK=32, 3-stage ----------------
// act: 0 none, 1 gelu+round, 2 round, 3 round * g_noedge[row>>5]
template<bool SK>
__global__ __launch_bounds__(128) void gemmA(
    const float* __restrict__ A0, const float* __restrict__ A1,
    const float* __restrict__ W0, const float* __restrict__ bias0, float* __restrict__ C0,
    const float* __restrict__ W1, const float* __restrict__ bias1, float* __restrict__ C1,
    int Mr, int Nc, int Kd, int act, int nsplit)
{
    extern __shared__ float dsm[];
    float (*As)[GA_STRIDE] = (float(*)[GA_STRIDE])dsm;
    float (*Ws)[GA_STRIDE] = (float(*)[GA_STRIDE])(dsm + 3*64*GA_STRIDE);

    const float* A;
    const float* W;
    const float* bias;
    float* C;
    int kbase = 0, nIter;
    if (SK) {
        A = A0; W = W0; bias = bias0;
        const int Kc = Kd / nsplit;
        kbase = blockIdx.z * Kc;
        nIter = Kc / 32;
        C = C0 + (size_t)blockIdx.z * Mr * Nc;
    } else {
        A    = blockIdx.z ? A1 : A0;
        W    = blockIdx.z ? W1 : W0;
        bias = blockIdx.z ? bias1 : bias0;
        C    = blockIdx.z ? C1 : C0;
        nIter = Kd / 32;
    }

    const int tid  = threadIdx.x;
    const int warp = tid >> 5, lane = tid & 31;
    const int wy   = warp >> 1, wx = warp & 1;
    const int grp  = lane >> 2, tig = lane & 3;
    const int row0 = blockIdx.y * 64;
    const int col0 = blockIdx.x * 64;
    const int lr   = tid >> 3;
    const int lk   = (tid & 7) * 4;

    const unsigned int sA = (unsigned int)__cvta_generic_to_shared(dsm);
    const unsigned int sW = (unsigned int)__cvta_generic_to_shared(dsm + 3*64*GA_STRIDE);
    const int v0s = (row0 + lr      < Mr) ? 16 : 0;
    const int v1s = (row0 + lr + 16 < Mr) ? 16 : 0;
    const int v2s = (row0 + lr + 32 < Mr) ? 16 : 0;
    const int v3s = (row0 + lr + 48 < Mr) ? 16 : 0;

    float acc[2][4][4] = {};

    #define ISSUE(st, itv)                                                              \
    {                                                                                   \
        const int k0 = kbase + (itv) * 32;                                              \
        cp16(sA + (((st)*64 + lr     )*GA_STRIDE + lk)*4, &A[(size_t)(row0+lr   ) * Kd + k0 + lk], v0s); \
        cp16(sA + (((st)*64 + lr + 16)*GA_STRIDE + lk)*4, &A[(size_t)(row0+lr+16) * Kd + k0 + lk], v1s); \
        cp16(sA + (((st)*64 + lr + 32)*GA_STRIDE + lk)*4, &A[(size_t)(row0+lr+32) * Kd + k0 + lk], v2s); \
        cp16(sA + (((st)*64 + lr + 48)*GA_STRIDE + lk)*4, &A[(size_t)(row0+lr+48) * Kd + k0 + lk], v3s); \
        cp16(sW + (((st)*64 + lr     )*GA_STRIDE + lk)*4, &W[(size_t)(col0+lr   ) * Kd + k0 + lk], 16); \
        cp16(sW + (((st)*64 + lr + 16)*GA_STRIDE + lk)*4, &W[(size_t)(col0+lr+16) * Kd + k0 + lk], 16); \
        cp16(sW + (((st)*64 + lr + 32)*GA_STRIDE + lk)*4, &W[(size_t)(col0+lr+32) * Kd + k0 + lk], 16); \
        cp16(sW + (((st)*64 + lr + 48)*GA_STRIDE + lk)*4, &W[(size_t)(col0+lr+48) * Kd + k0 + lk], 16); \
    }

    ISSUE(0, 0);
    asm volatile("cp.async.commit_group;");
    if (nIter > 1) ISSUE(1, 1);
    asm volatile("cp.async.commit_group;");

    for (int it = 0; it < nIter; it++) {
        asm volatile("cp.async.wait_group 1;");
        __syncthreads();

        if (it + 2 < nIter) ISSUE((it + 2) % 3, it + 2);
        asm volatile("cp.async.commit_group;");

        const int buf = it % 3;
        #pragma unroll
        for (int ks = 0; ks < 4; ks++) {
            const int kb = ks * 8;
            unsigned aH[2][4], bH[4][2];
            #pragma unroll
            for (int mt = 0; mt < 2; mt++) {
                const int mr = buf * 64 + wy * 32 + mt * 16 + grp;
                aH[mt][0] = __float_as_uint(As[mr    ][kb + tig]);
                aH[mt][1] = __float_as_uint(As[mr + 8][kb + tig]);
                aH[mt][2] = __float_as_uint(As[mr    ][kb + tig + 4]);
                aH[mt][3] = __float_as_uint(As[mr + 8][kb + tig + 4]);
            }
            #pragma unroll
            for (int nt = 0; nt < 4; nt++) {
                const int nc = buf * 64 + wx * 32 + nt * 8 + grp;
                bH[nt][0] = __float_as_uint(Ws[nc][kb + tig]);
                bH[nt][1] = __float_as_uint(Ws[nc][kb + tig + 4]);
            }
            #pragma unroll
            for (int mt = 0; mt < 2; mt++)
                #pragma unroll
                for (int nt = 0; nt < 4; nt++)
                    mma_tf32(acc[mt][nt], aH[mt], bH[nt]);
        }
        __syncthreads();
    }
    #undef ISSUE

    #pragma unroll
    for (int mt = 0; mt < 2; mt++) {
        const int r0 = row0 + wy * 32 + mt * 16 + grp;
        const int r1 = r0 + 8;
        #pragma unroll
        for (int nt = 0; nt < 4; nt++) {
            const int gc = col0 + wx * 32 + nt * 8 + tig * 2;
            float v0 = acc[mt][nt][0], v1 = acc[mt][nt][1];
            float v2 = acc[mt][nt][2], v3 = acc[mt][nt][3];
            if (!SK) {
                const float b0 = bias[gc], b1 = bias[gc + 1];
                v0 += b0; v1 += b1; v2 += b0; v3 += b1;
                if (act == 1) {
                    v0 = rtf(0.5f * v0 * (1.f + erff(v0 * 0.70710678118654752f)));
                    v1 = rtf(0.5f * v1 * (1.f + erff(v1 * 0.70710678118654752f)));
                    v2 = rtf(0.5f * v2 * (1.f + erff(v2 * 0.70710678118654752f)));
                    v3 = rtf(0.5f * v3 * (1.f + erff(v3 * 0.70710678118654752f)));
                } else if (act == 2) {
                    v0 = rtf(v0); v1 = rtf(v1); v2 = rtf(v2); v3 = rtf(v3);
                } else if (act == 3) {
                    float n0f = g_noedge[r0 >> 5], n1f = g_noedge[r1 >> 5];
                    v0 = rtf(v0 * n0f); v1 = rtf(v1 * n0f);
                    v2 = rtf(v2 * n1f); v3 = rtf(v3 * n1f);
                }
            }
            if (r0 < Mr) *(float2*)&C[(size_t)r0 * Nc + gc] = make_float2(v0, v1);
            if (r1 < Mr) *(float2*)&C[(size_t)r1 * Nc + gc] = make_float2(v2, v3);
        }
    }
}

// ---------------- cp.async split-tf32 GEMM (relproj): 3-stage, 4 smem streams ----------
__global__ __launch_bounds__(128) void gemmA_split(
    const float* __restrict__ Ahi, const float* __restrict__ Alo,
    const float* __restrict__ Whi, const float* __restrict__ Wlo,
    const float* __restrict__ bias, float* __restrict__ C,
    int Mr, int Nc, int Kd)
{
    extern __shared__ float dsm[];
    float (*SM)[GA_STRIDE] = (float(*)[GA_STRIDE])dsm;

    const int tid  = threadIdx.x;
    const int warp = tid >> 5, lane = tid & 31;
    const int wy   = warp >> 1, wx = warp & 1;
    const int grp  = lane >> 2, tig = lane & 3;
    const int row0 = blockIdx.y * 64;
    const int col0 = blockIdx.x * 64;
    const int lr   = tid >> 3;
    const int lk   = (tid & 7) * 4;

    const unsigned int sB = (unsigned int)__cvta_generic_to_shared(dsm);
    const int v0s = (row0 + lr      < Mr) ? 16 : 0;
    const int v1s = (row0 + lr + 16 < Mr) ? 16 : 0;
    const int v2s = (row0 + lr + 32 < Mr) ? 16 : 0;
    const int v3s = (row0 + lr + 48 < Mr) ? 16 : 0;

    const int nIter = Kd / 32;
    float acc[2][4][4] = {};

    // stream base row offsets inside a stage: AH=0, AL=64, WH=128, WL=192
    #define SISSUE(st, itv)                                                             \
    {                                                                                   \
        const int k0 = (itv) * 32;                                                      \
        const int sb = (st) * 256;                                                      \
        cp16(sB + ((sb       + lr     )*GA_STRIDE + lk)*4, &Ahi[(size_t)(row0+lr   ) * Kd + k0 + lk], v0s); \
        cp16(sB + ((sb       + lr + 16)*GA_STRIDE + lk)*4, &Ahi[(size_t)(row0+lr+16) * Kd + k0 + lk], v1s); \
        cp16(sB + ((sb       + lr + 32)*GA_STRIDE + lk)*4, &Ahi[(size_t)(row0+lr+32) * Kd + k0 + lk], v2s); \
        cp16(sB + ((sb       + lr + 48)*GA_STRIDE + lk)*4, &Ahi[(size_t)(row0+lr+48) * Kd + k0 + lk], v3s); \
        cp16(sB + ((sb + 64  + lr     )*GA_STRIDE + lk)*4, &Alo[(size_t)(row0+lr   ) * Kd + k0 + lk], v0s); \
        cp16(sB + ((sb + 64  + lr + 16)*GA_STRIDE + lk)*4, &Alo[(size_t)(row0+lr+16) * Kd + k0 + lk], v1s); \
        cp16(sB + ((sb + 64  + lr + 32)*GA_STRIDE + lk)*4, &Alo[(size_t)(row0+lr+32) * Kd + k0 + lk], v2s); \
        cp16(sB + ((sb + 64  + lr + 48)*GA_STRIDE + lk)*4, &Alo[(size_t)(row0+lr+48) * Kd + k0 + lk], v3s); \
        cp16(sB + ((sb + 128 + lr     )*GA_STRIDE + lk)*4, &Whi[(size_t)(col0+lr   ) * Kd + k0 + lk], 16); \
        cp16(sB + ((sb + 128 + lr + 16)*GA_STRIDE + lk)*4, &Whi[(size_t)(col0+lr+16) * Kd + k0 + lk], 16); \
        cp16(sB + ((sb + 128 + lr + 32)*GA_STRIDE + lk)*4, &Whi[(size_t)(col0+lr+32) * Kd + k0 + lk], 16); \
        cp16(sB + ((sb + 128 + lr + 48)*GA_STRIDE + lk)*4, &Whi[(size_t)(col0+lr+48) * Kd + k0 + lk], 16); \
        cp16(sB + ((sb + 192 + lr     )*GA_STRIDE + lk)*4, &Wlo[(size_t)(col0+lr   ) * Kd + k0 + lk], 16); \
        cp16(sB + ((sb + 192 + lr + 16)*GA_STRIDE + lk)*4, &Wlo[(size_t)(col0+lr+16) * Kd + k0 + lk], 16); \
        cp16(sB + ((sb + 192 + lr + 32)*GA_STRIDE + lk)*4, &Wlo[(size_t)(col0+lr+32) * Kd + k0 + lk], 16); \
        cp16(sB + ((sb + 192 + lr + 48)*GA_STRIDE + lk)*4, &Wlo[(size_t)(col0+lr+48) * Kd + k0 + lk], 16); \
    }

    SISSUE(0, 0);
    asm volatile("cp.async.commit_group;");
    if (nIter > 1) SISSUE(1, 1);
    asm volatile("cp.async.commit_group;");

    for (int it = 0; it < nIter; it++) {
        asm volatile("cp.async.wait_group 1;");
        __syncthreads();

        if (it + 2 < nIter) SISSUE((it + 2) % 3, it + 2);
        asm volatile("cp.async.commit_group;");

        const int sb = (it % 3) * 256;
        #pragma unroll
        for (int ks = 0; ks < 4; ks++) {
            const int kb = ks * 8;
            unsigned aH[2][4], aL[2][4], bH[4][2], bL[4][2];
            #pragma unroll
            for (int mt = 0; mt < 2; mt++) {
                const int mr = sb + wy * 32 + mt * 16 + grp;
                aH[mt][0] = __float_as_uint(SM[mr    ][kb + tig]);
                aH[mt][1] = __float_as_uint(SM[mr + 8][kb + tig]);
                aH[mt][2] = __float_as_uint(SM[mr    ][kb + tig + 4]);
                aH[mt][3] = __float_as_uint(SM[mr + 8][kb + tig + 4]);
                aL[mt][0] = __float_as_uint(SM[mr + 64    ][kb + tig]);
                aL[mt][1] = __float_as_uint(SM[mr + 64 + 8][kb + tig]);
                aL[mt][2] = __float_as_uint(SM[mr + 64    ][kb + tig + 4]);
                aL[mt][3] = __float_as_uint(SM[mr + 64 + 8][kb + tig + 4]);
            }
            #pragma unroll
            for (int nt = 0; nt < 4; nt++) {
                const int nc = sb + 128 + wx * 32 + nt * 8 + grp;
                bH[nt][0] = __float_as_uint(SM[nc][kb + tig]);
                bH[nt][1] = __float_as_uint(SM[nc][kb + tig + 4]);
                bL[nt][0] = __float_as_uint(SM[nc + 64][kb + tig]);
                bL[nt][1] = __float_as_uint(SM[nc + 64][kb + tig + 4]);
            }
            #pragma unroll
            for (int mt = 0; mt < 2; mt++)
                #pragma unroll
                for (int nt = 0; nt < 4; nt++) {
                    mma_tf32(acc[mt][nt], aH[mt], bH[nt]);
                    mma_tf32(acc[mt][nt], aH[mt], bL[nt]);
                    mma_tf32(acc[mt][nt], aL[mt], bH[nt]);
                }
        }
        __syncthreads();
    }
    #undef SISSUE

    #pragma unroll
    for (int mt = 0; mt < 2; mt++) {
        const int r0 = row0 + wy * 32 + mt * 16 + grp;
        const int r1 = r0 + 8;
        #pragma unroll
        for (int nt = 0; nt < 4; nt++) {
            const int gc = col0 + wx * 32 + nt * 8 + tig * 2;
            const float b0 = bias[gc], b1 = bias[gc + 1];
            if (r0 < Mr) *(float2*)&C[(size_t)r0 * Nc + gc] =
                make_float2(acc[mt][nt][0] + b0, acc[mt][nt][1] + b1);
            if (r1 < Mr) *(float2*)&C[(size_t)r1 * Nc + gc] =
                make_float2(acc[mt][nt][2] + b0, acc[mt][nt][3] + b1);
        }
    }
}

// ---------------- composed bias ----------------
__global__ void bias_combine(const float* __restrict__ ly_ow,
                             const float* __restrict__ ly_vb,
                             const float* __restrict__ ly_ob)
{
    int gw = blockIdx.x * 8 + (threadIdx.x >> 5);
    int lane = threadIdx.x & 31;
    int l = gw >> 9, row = gw & 511;
    const float* Ow = ly_ow + (size_t)l * D_ * D_ + (size_t)row * D_;
    const float* vb = ly_vb + (size_t)l * D_;
    float s = 0.f;
    #pragma unroll
    for (int k = 0; k < 4; k++) {
        int idx = (k * 32 + lane) * 4;
        float4 a = *(const float4*)&Ow[idx];
        float4 v = *(const float4*)&vb[idx];
        s += a.x * v.x + a.y * v.y + a.z * v.z + a.w * v.w;
    }
    #pragma unroll
    for (int o = 16; o; o >>= 1) s += __shfl_down_sync(0xffffffffu, s, o);
    if (lane == 0) g_bc[l * D_ + row] = s + ly_ob[l * D_ + row];
}

// ---------------- per-row inverse norm (warp per row) ----------------
__global__ void rownorm_kernel()
{
    int r = blockIdx.x * 8 + (threadIdx.x >> 5);
    int lane = threadIdx.x & 31;
    const float* row = &g_relproj[(size_t)r * D_];
    float s = 0.f;
    #pragma unroll
    for (int k = 0; k < 4; k++) {
        float4 v = *(const float4*)&row[(k * 32 + lane) * 4];
        s += v.x*v.x + v.y*v.y + v.z*v.z + v.w*v.w;
    }
    #pragma unroll
    for (int o = 16; o; o >>= 1) s += __shfl_down_sync(0xffffffffu, s, o);
    if (lane == 0) g_inorm[r] = 1.f / fmaxf(sqrtf(s), 1e-12f);
}

// ---------------- fused sims / top-8 / mean agg ----------------
__global__ void sims_topk_agg(const int* __restrict__ eids, const int* __restrict__ nids)
{
    int be = blockIdx.x;
    __shared__ float rn[D_];
    __shared__ float sims[N_];
    __shared__ int   topid[K_];

    int eid = eids[be];
    float ei = g_inorm[eid];
    for (int d = threadIdx.x; d < D_; d += 256) {
        float v = g_relproj[(size_t)eid * D_ + d];
        g_states[(size_t)be * D_ + d] = rtf(v);
        rn[d] = v * ei;
    }
    __syncthreads();

    int warp = threadIdx.x >> 5, lane = threadIdx.x & 31;
    for (int n = warp; n < N_; n += 8) {
        int nid = nids[(size_t)be * N_ + n];
        const float* row = &g_relproj[(size_t)nid * D_];
        float s = 0.f;
        for (int d = lane; d < D_; d += 32) s += row[d] * rn[d];
        #pragma unroll
        for (int o = 16; o; o >>= 1) s += __shfl_down_sync(0xffffffffu, s, o);
        if (lane == 0) sims[n] = s * g_inorm[nid];
    }
    __syncthreads();

    if (threadIdx.x == 0) {
        unsigned used = 0;
        for (int j = 0; j < K_; j++) {
            float best = -FLT_MAX; int bi = 0;
            for (int n = 0; n < N_; n++) {
                if ((used >> n) & 1u) continue;
                if (sims[n] > best) { best = sims[n]; bi = n; }
            }
            used |= 1u << bi;
            topid[j] = nids[(size_t)be * N_ + bi];
        }
    }
    __syncthreads();

    for (int d = threadIdx.x; d < D_; d += 256) {
        float acc = 0.f;
        #pragma unroll
        for (int j = 0; j < K_; j++) acc += g_relproj[(size_t)topid[j] * D_ + d];
        g_agg[(size_t)be * D_ + d] = rtf(acc * (1.f / K_));
    }
}

// ---------------- residual + layernorm; warp-shuffle reductions ----------
template<bool SKMODE>
__global__ void add_ln_kernel(const float* __restrict__ addp,
                              const float* __restrict__ bias,
                              const float* __restrict__ gamma, const float* __restrict__ beta,
                              const float* __restrict__ mask)
{
    int r = blockIdx.x;
    int t = threadIdx.x;
    const int warp = t >> 5, lane = t & 31;
    __shared__ float pw[8];
    __shared__ float bc;

    float a0, a1;
    if (SKMODE) {
        size_t o0 = (size_t)r*D_ + t, o1 = o0 + 256;
        a0 = g_part[o0] + g_part[(size_t)BE_*D_ + o0] + g_part[2*(size_t)BE_*D_ + o0]
           + g_part[3*(size_t)BE_*D_ + o0] + bias[t];
        a1 = g_part[o1] + g_part[(size_t)BE_*D_ + o1] + g_part[2*(size_t)BE_*D_ + o1]
           + g_part[3*(size_t)BE_*D_ + o1] + bias[t + 256];
    } else {
        a0 = addp[(size_t)r*D_ + t];
        a1 = addp[(size_t)r*D_ + t + 256];
    }
    float x0 = g_states[(size_t)r*D_ + t]       + a0;
    float x1 = g_states[(size_t)r*D_ + t + 256] + a1;

    float s = x0 + x1;
    #pragma unroll
    for (int o = 16; o; o >>= 1) s += __shfl_xor_sync(0xffffffffu, s, o);
    if (lane == 0) pw[warp] = s;
    __syncthreads();
    if (warp == 0) {
        float v = (lane < 8) ? pw[lane] : 0.f;
        #pragma unroll
        for (int o = 4; o; o >>= 1) v += __shfl_xor_sync(0xffffffffu, v, o);
        if (lane == 0) bc = v * (1.f / D_);
    }
    __syncthreads();
    float mu = bc;

    float d0 = x0 - mu, d1 = x1 - mu;
    s = d0*d0 + d1*d1;
    #pragma unroll
    for (int o = 16; o; o >>= 1) s += __shfl_xor_sync(0xffffffffu, s, o);
    if (lane == 0) pw[warp] = s;
    __syncthreads();
    if (warp == 0) {
        float v = (lane < 8) ? pw[lane] : 0.f;
        #pragma unroll
        for (int o = 4; o; o >>= 1) v += __shfl_xor_sync(0xffffffffu, v, o);
        if (lane == 0) bc = rsqrtf(v * (1.f / D_) + 1e-5f);
    }
    __syncthreads();
    float inv = bc;

    float mf = mask ? mask[r] : 1.f;
    g_states[(size_t)r*D_ + t]       = rtf((d0 * inv * gamma[t]     + beta[t])     * mf);
    g_states[(size_t)r*D_ + t + 256] = rtf((d1 * inv * gamma[t+256] + beta[t+256]) * mf);
}

// ---------------- memory-token cross attention ----------------
#define ETILE 16
__global__ __launch_bounds__(256) void mem_attn2(const float* __restrict__ edge_mask)
{
    const int b = blockIdx.x >> 3;
    const int h = blockIdx.x & 7;
    const int tid = threadIdx.x;

    __shared__ float Qs[M_][DH_ + 1];
    __shared__ float S[M_][E_];
    __shared__ float KV[ETILE][DH_ + 1];

    for (int i = tid; i < M_ * DH_; i += 256) {
        int m = i >> 6, d = i & 63;
        Qs[m][d] = g_q[(size_t)m * D_ + h * DH_ + d];
    }

    const float* mk = &edge_mask[(size_t)b * E_];
    const float* kb = &g_k[(size_t)b * E_ * D_ + h * DH_];
    const float* vb = &g_v[(size_t)b * E_ * D_ + h * DH_];
    __syncthreads();

    for (int et = 0; et < E_ / ETILE; et++) {
        for (int i = tid; i < ETILE * DH_; i += 256) {
            int e = i >> 6, d = i & 63;
            KV[e][d] = kb[(size_t)(et * ETILE + e) * D_ + d];
        }
        __syncthreads();
        #pragma unroll
        for (int p = 0; p < 2; p++) {
            int idx = tid * 2 + p;
            int m = idx >> 4, e = idx & 15;
            float s = 0.f;
            #pragma unroll 8
            for (int d = 0; d < DH_; d++) s += Qs[m][d] * KV[e][d];
            int eg = et * ETILE + e;
            S[m][eg] = (mk[eg] == 0.f) ? -FLT_MAX : s * 0.125f;
        }
        __syncthreads();
    }

    {
        const int warp = tid >> 5, lane = tid & 31;
        for (int r = 0; r < 4; r++) {
            const int m = warp * 4 + r;
            float mx = -FLT_MAX;
            for (int e = lane; e < E_; e += 32) mx = fmaxf(mx, S[m][e]);
            #pragma unroll
            for (int o = 16; o; o >>= 1) mx = fmaxf(mx, __shfl_xor_sync(0xffffffffu, mx, o));
            float sum = 0.f;
            for (int e = lane; e < E_; e += 32) {
                float w = expf(S[m][e] - mx);
                S[m][e] = w;
                sum += w;
            }
            #pragma unroll
            for (int o = 16; o; o >>= 1) sum += __shfl_xor_sync(0xffffffffu, sum, o);
            float inv = 1.f / sum;
            for (int e = lane; e < E_; e += 32) S[m][e] *= inv;
        }
    }
    __syncthreads();

    const int m  = tid >> 3;
    const int d0 = (tid & 7) * 8;
    float acc[8] = {};
    for (int vt = 0; vt < E_ / ETILE; vt++) {
        for (int i = tid; i < ETILE * DH_; i += 256) {
            int e = i >> 6, d = i & 63;
            KV[e][d] = vb[(size_t)(vt * ETILE + e) * D_ + d];
        }
        __syncthreads();
        #pragma unroll
        for (int e = 0; e < ETILE; e++) {
            float w = S[m][vt * ETILE + e];
            #pragma unroll
            for (int j = 0; j < 8; j++) acc[j] += w * KV[e][d0 + j];
        }
        __syncthreads();
    }
    size_t o = (size_t)(b * M_ + m) * D_ + h * DH_ + d0;
    #pragma unroll
    for (int j = 0; j < 8; j++) g_mem[o + j] = rtf(acc[j]);
}

// ---------------- no-edge flags ----------------
__global__ void noedge_flags(const float* __restrict__ edge_mask)
{
    int b = blockIdx.x;
    __shared__ float red[256];
    red[threadIdx.x] = edge_mask[(size_t)b * E_ + threadIdx.x];
    __syncthreads();
    for (int s = 128; s; s >>= 1) { if (threadIdx.x < s) red[threadIdx.x] += red[threadIdx.x+s]; __syncthreads(); }
    if (threadIdx.x == 0) g_noedge[b] = (red[0] == 0.f) ? 0.f : 1.f;
}

// ---------------- host launch ----------------
static inline dim3 g64(int Mr, int Nc, int z = 1) {
    return dim3(Nc / 64, (Mr + 63) / 64, z);
}

extern "C" void kernel_launch(void* const* d_in, const int* in_sizes, int n_in,
                              void* d_out, int out_size)
{
    const int*   edge_rel_ids = (const int*)  d_in[0];
    const int*   neigh_ids    = (const int*)  d_in[1];
    const float* edge_mask    = (const float*)d_in[2];
    const float* rel_emb      = (const float*)d_in[3];
    const float* rp_w         = (const float*)d_in[4];
    const float* rp_b         = (const float*)d_in[5];
    const float* ly_vw        = (const float*)d_in[6];
    const float* ly_vb        = (const float*)d_in[7];
    const float* ly_ow        = (const float*)d_in[8];
    const float* ly_ob        = (const float*)d_in[9];
    const float* ly_n1g       = (const float*)d_in[10];
    const float* ly_n1b       = (const float*)d_in[11];
    const float* ly_n2g       = (const float*)d_in[12];
    const float* ly_n2b       = (const float*)d_in[13];
    const float* ly_w1        = (const float*)d_in[14];
    const float* ly_b1        = (const float*)d_in[15];
    const float* ly_w2        = (const float*)d_in[16];
    const float* ly_b2        = (const float*)d_in[17];
    const float* mem_q        = (const float*)d_in[18];
    const float* t_qw         = (const float*)d_in[19];
    const float* t_qb         = (const float*)d_in[20];
    const float* t_kw         = (const float*)d_in[21];
    const float* t_kb         = (const float*)d_in[22];
    const float* t_vw         = (const float*)d_in[23];
    const float* t_vb         = (const float*)d_in[24];
    const float* t_ow         = (const float*)d_in[25];
    const float* t_ob         = (const float*)d_in[26];
    const float* proj_w       = (const float*)d_in[27];
    const float* proj_b       = (const float*)d_in[28];
    float* out = (float*)d_out;

    float *p_relproj, *p_states, *p_agg, *p_attn0, *p_attn1, *p_h, *p_part;
    float *p_wc, *p_bc, *p_zero, *p_q, *p_k, *p_v, *p_mem, *p_memo;
    float *p_w1r, *p_w2r, *p_kvwr, *p_pwr, *p_owr, *p_vwT, *p_qr, *p_qwr, *p_towr;
    float *p_ehi, *p_elo, *p_whi, *p_wlo;
    cudaGetSymbolAddress((void**)&p_relproj, g_relproj);
    cudaGetSymbolAddress((void**)&p_states,  g_states);
    cudaGetSymbolAddress((void**)&p_agg,     g_agg);
    cudaGetSymbolAddress((void**)&p_attn0,   g_attn0);
    cudaGetSymbolAddress((void**)&p_attn1,   g_attn1);
    cudaGetSymbolAddress((void**)&p_h,       g_h);
    cudaGetSymbolAddress((void**)&p_part,    g_part);
    cudaGetSymbolAddress((void**)&p_wc,      g_wc);
    cudaGetSymbolAddress((void**)&p_bc,      g_bc);
    cudaGetSymbolAddress((void**)&p_zero,    g_zero);
    cudaGetSymbolAddress((void**)&p_q,       g_q);
    cudaGetSymbolAddress((void**)&p_k,       g_k);
    cudaGetSymbolAddress((void**)&p_v,       g_v);
    cudaGetSymbolAddress((void**)&p_mem,     g_mem);
    cudaGetSymbolAddress((void**)&p_memo,    g_memo);
    cudaGetSymbolAddress((void**)&p_w1r,     g_w1r);
    cudaGetSymbolAddress((void**)&p_w2r,     g_w2r);
    cudaGetSymbolAddress((void**)&p_kvwr,    g_kvwr);
    cudaGetSymbolAddress((void**)&p_pwr,     g_pwr);
    cudaGetSymbolAddress((void**)&p_owr,     g_owr);
    cudaGetSymbolAddress((void**)&p_vwT,     g_vwT);
    cudaGetSymbolAddress((void**)&p_qr,      g_qr);
    cudaGetSymbolAddress((void**)&p_qwr,     g_qwr);
    cudaGetSymbolAddress((void**)&p_towr,    g_towr);
    cudaGetSymbolAddress((void**)&p_ehi,     g_ehi);
    cudaGetSymbolAddress((void**)&p_elo,     g_elo);
    cudaGetSymbolAddress((void**)&p_whi,     g_whi);
    cudaGetSymbolAddress((void**)&p_wlo,     g_wlo);

    cudaFuncSetAttribute(gemmA<false>, cudaFuncAttributeMaxDynamicSharedMemorySize, GA_SMEM);
    cudaFuncSetAttribute(gemmA<true>,  cudaFuncAttributeMaxDynamicSharedMemorySize, GA_SMEM);
    cudaFuncSetAttribute(gemmA_split,  cudaFuncAttributeMaxDynamicSharedMemorySize, GS_SMEM);

    // 0) prep: pre-round, hi/lo split, Vw transpose
    {
        RoundSegs rs;
        rs.s[0] = ly_w1;  rs.d[0] = p_w1r;  rs.n[0] = L_*4*D_*D_/4;
        rs.s[1] = ly_w2;  rs.d[1] = p_w2r;  rs.n[1] = L_*4*D_*D_/4;
        rs.s[2] = t_kw;   rs.d[2] = p_kvwr; rs.n[2] = D_*D_/4;
        rs.s[3] = t_vw;   rs.d[3] = p_kvwr + (size_t)D_*D_; rs.n[3] = D_*D_/4;
        rs.s[4] = proj_w; rs.d[4] = p_pwr;  rs.n[4] = HLLM_*D_/4;
        rs.s[5] = ly_ow;  rs.d[5] = p_owr;  rs.n[5] = 2*D_*D_/4;
        rs.s[6] = mem_q;  rs.d[6] = p_qr;   rs.n[6] = M_*D_/4;
        rs.s[7] = t_qw;   rs.d[7] = p_qwr;  rs.n[7] = D_*D_/4;
        rs.s[8] = t_ow;   rs.d[8] = p_towr; rs.n[8] = D_*D_/4;
        int total = 0;
        for (int k = 0; k < 9; k++) total += rs.n[k];
        round_allN<<<(total + 255)/256, 256>>>(rs);
        round_split2<<<((R_*RD_ + D_*RD_)/4 + 255)/256, 256>>>(
            rel_emb, p_ehi, p_elo, R_*RD_/4,
            rp_w,    p_whi, p_wlo, D_*RD_/4);
        transpose_round<<<dim3(16,16,2), 256>>>(ly_vw, p_vwT);
    }

    // 1) relation table projection (split-tf32, 3-stage async)
    gemmA_split<<<g64(R_, D_), 128, GS_SMEM>>>(p_ehi, p_elo, p_whi, p_wlo,
                                               rp_b, p_relproj, R_, D_, RD_);
    rownorm_kernel<<<R_/8, 256>>>();

    // 2) compose out_l∘v_l
    gemmA<false><<<g64(D_, D_, 2), 128, GA_SMEM>>>(
        p_owr, p_owr + (size_t)D_*D_,
        p_vwT, p_zero, p_wc,
        p_vwT + (size_t)D_*D_, p_zero, p_wc + (size_t)D_*D_,
        D_, D_, D_, 2, 1);
    bias_combine<<<128, 256>>>(ly_ow, ly_vb, ly_ob);

    // 3) sims / top-8 / agg
    sims_topk_agg<<<BE_, 256>>>(edge_rel_ids, neigh_ids);

    // 4) attention branch
    gemmA<false><<<g64(BE_, D_, 2), 128, GA_SMEM>>>(
        p_agg, p_agg,
        p_wc, p_bc, p_attn0,
        p_wc + (size_t)D_*D_, p_bc + D_, p_attn1,
        BE_, D_, D_, 0, 1);

    // 5) relation-context layers
    for (int l = 0; l < L_; l++) {
        const float* w1r = p_w1r + (size_t)l * 4 * D_ * D_;
        const float* b1  = ly_b1 + (size_t)l * 4 * D_;
        const float* w2r = p_w2r + (size_t)l * D_ * 4 * D_;
        const float* b2  = ly_b2 + (size_t)l * D_;
        const float* attn = l ? p_attn1 : p_attn0;

        add_ln_kernel<false><<<BE_, 256>>>(attn, nullptr,
                                           ly_n1g + (size_t)l*D_, ly_n1b + (size_t)l*D_, nullptr);
        gemmA<false><<<g64(BE_, 4*D_), 128, GA_SMEM>>>(p_states, p_states, w1r, b1, p_h,
                                                       w1r, b1, p_h, BE_, 4*D_, D_, 1, 1);
        gemmA<true><<<g64(BE_, D_, KS_), 128, GA_SMEM>>>(p_h, p_h, w2r, nullptr, p_part,
                                                         nullptr, nullptr, nullptr,
                                                         BE_, D_, 4*D_, 0, KS_);
        add_ln_kernel<true><<<BE_, 256>>>(nullptr, b2,
                                          ly_n2g + (size_t)l*D_, ly_n2b + (size_t)l*D_, edge_mask);
    }

    // 6) memory tokenizer (noedge fused into memo epilogue)
    noedge_flags<<<B_, 256>>>(edge_mask);
    gemmA<false><<<g64(M_, D_), 128, GA_SMEM>>>(p_qr, p_qr, p_qwr, t_qb, p_q,
                                                p_qwr, t_qb, p_q, M_, D_, D_, 0, 1);
    gemmA<false><<<g64(BE_, D_, 2), 128, GA_SMEM>>>(p_states, p_states,
                                                    p_kvwr, t_kb, p_k,
                                                    p_kvwr + (size_t)D_*D_, t_vb, p_v,
                                                    BE_, D_, D_, 0, 1);
    mem_attn2<<<B_*HEADS_, 256>>>(edge_mask);
    gemmA<false><<<g64(BM_, D_), 128, GA_SMEM>>>(p_mem, p_mem, p_towr, t_ob, p_memo,
                                                 p_towr, t_ob, p_memo, BM_, D_, D_, 3, 1);

    // 7) final projection
    gemmA<false><<<g64(BM_, HLLM_), 128, GA_SMEM>>>(p_memo, p_memo, p_pwr, proj_b, out,
                                                    p_pwr, proj_b, out, BM_, HLLM_, D_, 0, 1);
}